// round 11
// baseline (speedup 1.0000x reference)
#include <cuda_runtime.h>
#include <cuda_bf16.h>
#include <mma.h>
#include <cstdint>
#include <math.h>

using namespace nvcuda;

#define BB 4
#define NN 512
#define BN 2048
#define CIN 1024
#define HH 48
#define WWW 48
#define CO 256
#define NPAIR 261632          // 512*511
#define KEDGE 4096
#define ETOT (4*KEDGE + BN)   // 18432 edges per graph type (incl self loops)
#define GOUT 512
#define FUS 768
#define RCLS 228
#define CCLS 116

// HMMA tile kernels: 128x128 CTA tile, K-chunk 64, 512 threads.
#define CLD   72
#define CMAT  18432
#define CSTG  73728            // 4 mats (Ah|Al|Bh|Bl)
#define CSMEM (2*CSTG + 256)   // 147712

// ---------------- device scratch ----------------
__device__ __align__(1024) float g_dec[BB*HH*WWW*CO];
__device__ __align__(1024) __nv_bfloat16 g_inh[BB*HH*WWW*CIN];
__device__ __align__(1024) __nv_bfloat16 g_inl[BB*HH*WWW*CIN];
__device__ __align__(1024) __nv_bfloat16 g_wh[9*CO*CIN];
__device__ __align__(1024) __nv_bfloat16 g_wl[9*CO*CIN];
__device__ __align__(1024) __nv_bfloat16 g_cnnh[BN*1024], g_cnnl[BN*1024];
__device__ __align__(1024) __nv_bfloat16 g_fush[BN*FUS], g_fusl[BN*FUS];
__device__ __align__(1024) __nv_bfloat16 g_wtch[512*1024], g_wtcl[512*1024];
__device__ __align__(1024) __nv_bfloat16 g_wtgh[2][512*768], g_wtgl[2][512*768];
__device__ float g_cy[BB*NN], g_cx[BB*NN];
__device__ float g_tbh[BB], g_tbw[BB];
__device__ unsigned long long g_keys[8][NPAIR];
__device__ unsigned long long g_cand[8][NPAIR];
__device__ int g_ncand[8];
__device__ unsigned long long g_prefix[8];
__device__ int g_kneed[8];
__device__ unsigned int g_hist[8][256];
__device__ int g_ecount[8];
__device__ int   g_esrc[2][ETOT], g_edst[2][ETOT];
__device__ float g_ew[2][ETOT];
__device__ float g_deg[2][BN];
__device__ float g_xw[2][BN*GOUT];
__device__ float g_feat[2][BN*GOUT];

// ---------------- helpers ----------------
__device__ __forceinline__ uint32_t s2u(const void* p) {
    uint32_t a;
    asm("{ .reg .u64 t; cvta.to.shared.u64 t, %1; cvt.u32.u64 %0, t; }" : "=r"(a) : "l"(p));
    return a;
}
__device__ __forceinline__ void cp16(uint32_t dst, const void* src, int sz) {
    asm volatile("cp.async.cg.shared.global [%0], [%1], 16, %2;" :: "r"(dst), "l"(src), "r"(sz));
}
__device__ __forceinline__ void cp16f(uint32_t dst, const void* src) {
    asm volatile("cp.async.cg.shared.global [%0], [%1], 16;" :: "r"(dst), "l"(src));
}
__device__ __forceinline__ void cp_commit() { asm volatile("cp.async.commit_group;" ::: "memory"); }
__device__ __forceinline__ void cp_wait1() { asm volatile("cp.async.wait_group 1;" ::: "memory"); }
__device__ __forceinline__ void cp_wait0() { asm volatile("cp.async.wait_group 0;" ::: "memory"); }
__device__ __forceinline__ void split_bf16(float v, __nv_bfloat16& h, __nv_bfloat16& l) {
    h = __float2bfloat16(v);
    l = __float2bfloat16(v - __bfloat162float(h));
}

// emit one edge (shared by compact + final emit)
__device__ __forceinline__ void emit_edge(int seg, unsigned long long k) {
    int pos = atomicAdd(&g_ecount[seg], 1);
    if (pos < KEDGE) {
        int b = seg & 3, ty = seg >> 2;
        unsigned p = (unsigned)k & 0xFFFFFFFFu;
        int i = p / 511, r = p % 511;
        int j = r + (r >= i ? 1 : 0);
        float v = __uint_as_float(~(unsigned)(k >> 32));
        int slot = b*KEDGE + pos;
        int dst = b*NN + j;
        g_esrc[ty][slot] = b*NN + i;
        g_edst[ty][slot] = dst;
        g_ew[ty][slot] = v;
        atomicAdd(&g_deg[ty][dst], v);
    }
}

// ---------------- init ----------------
__global__ void k_init() {
    int t = blockIdx.x * blockDim.x + threadIdx.x;
    if (t < 8) { g_prefix[t] = 0ULL; g_kneed[t] = KEDGE; g_ecount[t] = 0; g_ncand[t] = 0; }
    if (t < 8*256) ((unsigned*)g_hist)[t] = 0u;
    if (t < 2*BN) {
        int ty = t / BN, i = t % BN;
        g_deg[ty][i] = 1.f;             // self loop weight
        g_esrc[ty][4*KEDGE + i] = i;
        g_edst[ty][4*KEDGE + i] = i;
        g_ew[ty][4*KEDGE + i] = 1.f;
    }
    if (t < 2*BN*GOUT) ((float*)g_feat)[t] = 0.f;
}

// ---------------- input NCHW fp32 -> NHWC split bf16 ----------------
__global__ void __launch_bounds__(256) k_cvt_in(const float* __restrict__ in) {
    __shared__ float sT[64][17];
    int ci0 = blockIdx.x * 64, x0 = blockIdx.y * 16;
    int by = blockIdx.z; int b = by / 48, y = by % 48;
    int t = threadIdx.x;
    int lx = t & 15, lc = t >> 4;
    const float* src = in + (size_t)b * CIN * 2304 + (size_t)y * 48 + x0;
#pragma unroll
    for (int j = 0; j < 4; j++)
        sT[lc + 16*j][lx] = src[(size_t)(ci0 + lc + 16*j) * 2304 + lx];
    __syncthreads();
    int wc = t & 63, wx = t >> 6;
#pragma unroll
    for (int j = 0; j < 4; j++) {
        float v = sT[wc][wx + 4*j];
        __nv_bfloat16 h, l; split_bf16(v, h, l);
        size_t o = ((size_t)(b*2304 + y*48 + x0 + wx + 4*j)) * 1024 + ci0 + wc;
        g_inh[o] = h; g_inl[o] = l;
    }
}

// ---------------- conv weights -> [tap][co][ci] split bf16 ----------------
__global__ void k_cvt_w(const float* __restrict__ W) {
    int co = blockIdx.x;
    for (int ci = threadIdx.x; ci < 1024; ci += 256) {
        const float* wp = W + ((size_t)co * 1024 + ci) * 9;
#pragma unroll
        for (int tap = 0; tap < 9; tap++) {
            __nv_bfloat16 h, l; split_bf16(wp[tap], h, l);
            size_t o = ((size_t)(tap*256 + co)) * 1024 + ci;
            g_wh[o] = h; g_wl[o] = l;
        }
    }
}

// ---------------- W_cnn -> [n][p*256+c] split bf16 (perm folded) ----------------
__global__ void k_cvt_wcnn(const float* __restrict__ W) {
    int n = blockIdx.x;
    for (int kk = threadIdx.x; kk < 1024; kk += 256) {
        int p = kk >> 8, c = kk & 255;
        float v = W[(size_t)(c*4 + p) * 512 + n];
        __nv_bfloat16 h, l; split_bf16(v, h, l);
        g_wtch[(size_t)n*1024 + kk] = h;
        g_wtcl[(size_t)n*1024 + kk] = l;
    }
}

// ---------------- W_grow/W_gcol -> [n][k] split bf16 ----------------
__global__ void k_cvt_wg(const float* __restrict__ W0, const float* __restrict__ W1) {
    int n = blockIdx.x, ty = blockIdx.y;
    const float* W = ty ? W1 : W0;
    for (int k = threadIdx.x; k < 768; k += 256) {
        __nv_bfloat16 h, l; split_bf16(W[(size_t)k * 512 + n], h, l);
        g_wtgh[ty][(size_t)n*768 + k] = h;
        g_wtgl[ty][(size_t)n*768 + k] = l;
    }
}

// ---------------- conv as 9 shifted GEMMs, HMMA split-bf16, 512 thr ----------------
// grid (2, 72): x = co-half (128 co), y = M-tile of 128 pixels.
__global__ void __launch_bounds__(512, 1) k_conv_wmma(const float* __restrict__ bias) {
    extern __shared__ char dsm_raw[];
    uint32_t raw = s2u(dsm_raw);
    uint32_t pad = (128u - (raw & 127u)) & 127u;
    char* sp = dsm_raw + pad;
    uint32_t spu = raw + pad;

    int t = threadIdx.x, wid = t >> 5;
    int co0 = blockIdx.x * 128;
    int tileM = blockIdx.y;
    int b = tileM / 18, loc0 = (tileM % 18) * 128;
    int wm = wid & 3, wn = wid >> 2;   // warp tile 32x32

    const __nv_bfloat16* inh_b = g_inh + (size_t)b * 2304 * 1024;
    const __nv_bfloat16* inl_b = g_inl + (size_t)b * 2304 * 1024;

    int rowL[2], qL[2], pyL[2], pxL[2];
#pragma unroll
    for (int i = 0; i < 2; i++) {
        int idx = t + 512*i;
        rowL[i] = idx >> 3; qL[i] = idx & 7;
        int l = loc0 + rowL[i];
        pyL[i] = l / 48; pxL[i] = l % 48;
    }

    wmma::fragment<wmma::accumulator, 16, 16, 16, float> acc[2][2];
#pragma unroll
    for (int i = 0; i < 2; i++)
#pragma unroll
        for (int j = 0; j < 2; j++) wmma::fill_fragment(acc[i][j], 0.f);

#define ISSUE_CHUNK(c) do {                                                       \
        int tap_ = (c) >> 4, ci0_ = ((c) & 15) << 6;                              \
        int dy_ = tap_ / 3 - 1, dx_ = tap_ % 3 - 1;                               \
        uint32_t sb_ = spu + ((c) & 1) * CSTG;                                    \
        _Pragma("unroll")                                                         \
        for (int i = 0; i < 2; i++) {                                             \
            int row_ = rowL[i], q_ = qL[i];                                       \
            uint32_t so_ = (uint32_t)(row_*(CLD*2) + q_*16);                      \
            int ys_ = pyL[i] + dy_, xs_ = pxL[i] + dx_;                           \
            bool ok_ = ((unsigned)ys_ < 48u) & ((unsigned)xs_ < 48u);             \
            size_t go_ = ok_ ? ((size_t)(ys_*48 + xs_)*1024 + ci0_ + q_*8) : 0;   \
            int sz_ = ok_ ? 16 : 0;                                               \
            cp16(sb_ + so_,          inh_b + go_, sz_);                           \
            cp16(sb_ + CMAT + so_,   inl_b + go_, sz_);                           \
            size_t wo_ = (size_t)(tap_*256 + co0 + row_)*1024 + ci0_ + q_*8;      \
            cp16f(sb_ + 2*CMAT + so_, g_wh + wo_);                                \
            cp16f(sb_ + 3*CMAT + so_, g_wl + wo_);                                \
        }                                                                         \
    } while (0)

    ISSUE_CHUNK(0);
    cp_commit();

    for (int c = 0; c < 144; c++) {
        if (c + 1 < 144) { ISSUE_CHUNK(c + 1); cp_commit(); cp_wait1(); }
        else             { cp_wait0(); }
        __syncthreads();
        const char* sb = sp + (c & 1) * CSTG;
        const __nv_bfloat16* Ah = (const __nv_bfloat16*)(sb);
        const __nv_bfloat16* Al = (const __nv_bfloat16*)(sb + CMAT);
        const __nv_bfloat16* Bh = (const __nv_bfloat16*)(sb + 2*CMAT);
        const __nv_bfloat16* Bl = (const __nv_bfloat16*)(sb + 3*CMAT);
#pragma unroll
        for (int kk = 0; kk < 64; kk += 16) {
            wmma::fragment<wmma::matrix_a, 16, 16, 16, __nv_bfloat16, wmma::row_major> ah[2], al[2];
            wmma::fragment<wmma::matrix_b, 16, 16, 16, __nv_bfloat16, wmma::col_major> bh[2], bl[2];
#pragma unroll
            for (int i = 0; i < 2; i++) {
                wmma::load_matrix_sync(ah[i], Ah + (wm*32 + i*16)*CLD + kk, CLD);
                wmma::load_matrix_sync(al[i], Al + (wm*32 + i*16)*CLD + kk, CLD);
            }
#pragma unroll
            for (int j = 0; j < 2; j++) {
                wmma::load_matrix_sync(bh[j], Bh + (wn*32 + j*16)*CLD + kk, CLD);
                wmma::load_matrix_sync(bl[j], Bl + (wn*32 + j*16)*CLD + kk, CLD);
            }
#pragma unroll
            for (int i = 0; i < 2; i++)
#pragma unroll
                for (int j = 0; j < 2; j++) {
                    wmma::mma_sync(acc[i][j], ah[i], bh[j], acc[i][j]);
                    wmma::mma_sync(acc[i][j], al[i], bh[j], acc[i][j]);
                    wmma::mma_sync(acc[i][j], ah[i], bl[j], acc[i][j]);
                }
        }
        __syncthreads();
    }
#undef ISSUE_CHUNK

    float* sE = (float*)sp;
#pragma unroll
    for (int i = 0; i < 2; i++)
#pragma unroll
        for (int j = 0; j < 2; j++)
            wmma::store_matrix_sync(sE + (wm*32 + i*16)*128 + wn*32 + j*16,
                                    acc[i][j], 128, wmma::mem_row_major);
    __syncthreads();
#pragma unroll
    for (int r = 0; r < 8; r++) {
        int idx = t + 512*r;
        int row = idx >> 5, col = (idx & 31) * 4;
        float4 v = *(const float4*)&sE[row*128 + col];
        v.x = fmaxf(v.x + bias[co0+col+0], 0.f);
        v.y = fmaxf(v.y + bias[co0+col+1], 0.f);
        v.z = fmaxf(v.z + bias[co0+col+2], 0.f);
        v.w = fmaxf(v.w + bias[co0+col+3], 0.f);
        int pix = b*2304 + loc0 + row;
        *(float4*)&g_dec[(size_t)pix*256 + co0 + col] = v;
    }
}

// ---------------- split-bf16 HMMA GEMM: C[M,N] = A[M,K] * B[N,K]^T ----------------
template<int EPI>
__global__ void __launch_bounds__(512, 1) k_hgemm(const __nv_bfloat16* __restrict__ Agh,
                                                  const __nv_bfloat16* __restrict__ Agl,
                                                  const __nv_bfloat16* __restrict__ Bgh,
                                                  const __nv_bfloat16* __restrict__ Bgl,
                                                  float* C, __nv_bfloat16* Ch, __nv_bfloat16* Cl,
                                                  const float* __restrict__ bias,
                                                  int K, int ldc, int colofs) {
    extern __shared__ char dsm_raw[];
    uint32_t raw = s2u(dsm_raw);
    uint32_t pad = (128u - (raw & 127u)) & 127u;
    char* sp = dsm_raw + pad;
    uint32_t spu = raw + pad;

    int t = threadIdx.x, wid = t >> 5;
    int n0 = blockIdx.x * 128, m0 = blockIdx.y * 128;
    int wm = wid & 3, wn = wid >> 2;

    int rowL[2], qL[2];
#pragma unroll
    for (int i = 0; i < 2; i++) {
        int idx = t + 512*i;
        rowL[i] = idx >> 3; qL[i] = idx & 7;
    }

    wmma::fragment<wmma::accumulator, 16, 16, 16, float> acc[2][2];
#pragma unroll
    for (int i = 0; i < 2; i++)
#pragma unroll
        for (int j = 0; j < 2; j++) wmma::fill_fragment(acc[i][j], 0.f);

    int nch = K >> 6;
#define ISSUE_G(c) do {                                                          \
        int k0_ = (c) << 6;                                                      \
        uint32_t sb_ = spu + ((c) & 1) * CSTG;                                   \
        _Pragma("unroll")                                                        \
        for (int i = 0; i < 2; i++) {                                            \
            int row_ = rowL[i], q_ = qL[i];                                      \
            uint32_t so_ = (uint32_t)(row_*(CLD*2) + q_*16);                     \
            size_t ao_ = (size_t)(m0 + row_)*K + k0_ + q_*8;                     \
            cp16f(sb_ + so_,        Agh + ao_);                                  \
            cp16f(sb_ + CMAT + so_, Agl + ao_);                                  \
            size_t bo_ = (size_t)(n0 + row_)*K + k0_ + q_*8;                     \
            cp16f(sb_ + 2*CMAT + so_, Bgh + bo_);                                \
            cp16f(sb_ + 3*CMAT + so_, Bgl + bo_);                                \
        }                                                                        \
    } while (0)

    ISSUE_G(0);
    cp_commit();
    for (int c = 0; c < nch; c++) {
        if (c + 1 < nch) { ISSUE_G(c + 1); cp_commit(); cp_wait1(); }
        else             { cp_wait0(); }
        __syncthreads();
        const char* sb = sp + (c & 1) * CSTG;
        const __nv_bfloat16* Ah = (const __nv_bfloat16*)(sb);
        const __nv_bfloat16* Al = (const __nv_bfloat16*)(sb + CMAT);
        const __nv_bfloat16* Bh = (const __nv_bfloat16*)(sb + 2*CMAT);
        const __nv_bfloat16* Bl = (const __nv_bfloat16*)(sb + 3*CMAT);
#pragma unroll
        for (int kk = 0; kk < 64; kk += 16) {
            wmma::fragment<wmma::matrix_a, 16, 16, 16, __nv_bfloat16, wmma::row_major> ah[2], al[2];
            wmma::fragment<wmma::matrix_b, 16, 16, 16, __nv_bfloat16, wmma::col_major> bh[2], bl[2];
#pragma unroll
            for (int i = 0; i < 2; i++) {
                wmma::load_matrix_sync(ah[i], Ah + (wm*32 + i*16)*CLD + kk, CLD);
                wmma::load_matrix_sync(al[i], Al + (wm*32 + i*16)*CLD + kk, CLD);
            }
#pragma unroll
            for (int j = 0; j < 2; j++) {
                wmma::load_matrix_sync(bh[j], Bh + (wn*32 + j*16)*CLD + kk, CLD);
                wmma::load_matrix_sync(bl[j], Bl + (wn*32 + j*16)*CLD + kk, CLD);
            }
#pragma unroll
            for (int i = 0; i < 2; i++)
#pragma unroll
                for (int j = 0; j < 2; j++) {
                    wmma::mma_sync(acc[i][j], ah[i], bh[j], acc[i][j]);
                    wmma::mma_sync(acc[i][j], al[i], bh[j], acc[i][j]);
                    wmma::mma_sync(acc[i][j], ah[i], bl[j], acc[i][j]);
                }
        }
        __syncthreads();
    }
#undef ISSUE_G

    float* sE = (float*)sp;
#pragma unroll
    for (int i = 0; i < 2; i++)
#pragma unroll
        for (int j = 0; j < 2; j++)
            wmma::store_matrix_sync(sE + (wm*32 + i*16)*128 + wn*32 + j*16,
                                    acc[i][j], 128, wmma::mem_row_major);
    __syncthreads();
#pragma unroll
    for (int r = 0; r < 8; r++) {
        int idx = t + 512*r;
        int row = idx >> 5, col = (idx & 31) * 4;
        float4 v = *(const float4*)&sE[row*128 + col];
        if (EPI == 0) {
            *(float4*)&C[(size_t)(m0 + row)*ldc + n0 + col] = v;
        } else {
            v.x = fmaxf(v.x + bias[n0+col+0], 0.f);
            v.y = fmaxf(v.y + bias[n0+col+1], 0.f);
            v.z = fmaxf(v.z + bias[n0+col+2], 0.f);
            v.w = fmaxf(v.w + bias[n0+col+3], 0.f);
            __nv_bfloat16 h0,l0,h1,l1,h2,l2,h3,l3;
            split_bf16(v.x,h0,l0); split_bf16(v.y,h1,l1);
            split_bf16(v.z,h2,l2); split_bf16(v.w,h3,l3);
            size_t o = (size_t)(m0 + row)*ldc + colofs + n0 + col;
            __nv_bfloat162* ph = (__nv_bfloat162*)&Ch[o];
            __nv_bfloat162* pl = (__nv_bfloat162*)&Cl[o];
            ph[0] = __nv_bfloat162(h0, h1); ph[1] = __nv_bfloat162(h2, h3);
            pl[0] = __nv_bfloat162(l0, l1); pl[1] = __nv_bfloat162(l2, l3);
        }
    }
}

// ---------------- box feature MLP -> fusion split bf16 ----------------
__global__ void k_boxfeat(const float* __restrict__ boxes,
                          const float* __restrict__ Wb, const float* __restrict__ bb) {
    int n = blockIdx.x, co = threadIdx.x;
    float f0 = boxes[n*4+0], f1 = boxes[n*4+1], f2 = boxes[n*4+2], f3 = boxes[n*4+3];
    float cx = (f0 + f2) / 2.0f, cy = (f1 + f3) / 2.0f;
    float b0 = cx / 48.0f, b1 = cy / 48.0f;
    float b2 = (f2 - f0) / 48.0f, b3 = (f3 - f1) / 48.0f;
    float v = bb[co] + b0*Wb[co] + b1*Wb[256+co] + b2*Wb[512+co] + b3*Wb[768+co];
    v = fmaxf(v, 0.f);
    __nv_bfloat16 h, l; split_bf16(v, h, l);
    g_fush[(size_t)n*FUS + co] = h;
    g_fusl[(size_t)n*FUS + co] = l;
}

// ---------------- cx/cy + table extents ----------------
__global__ void k_cxcy(const float* __restrict__ boxes, const float* __restrict__ scales,
                       const float* __restrict__ pdls, const float* __restrict__ pdts) {
    int b = blockIdx.x, i = threadIdx.x;
    float sc = scales[b], pl = pdls[b], pt = pdts[b];
    const float* bx = boxes + ((size_t)b*NN + i)*4;
    float o0 = (bx[0]-pl)/sc, o1 = (bx[1]-pt)/sc, o2 = (bx[2]-pl)/sc, o3 = (bx[3]-pt)/sc;
    g_cx[b*NN+i] = (o0 + o2) * 0.5f;
    g_cy[b*NN+i] = (o1 + o3) * 0.5f;
    __shared__ float sw[512], sh[512];
    sw[i] = fmaxf(o0, o2); sh[i] = fmaxf(o1, o3);
    __syncthreads();
    for (int s = 256; s > 0; s >>= 1) {
        if (i < s) { sw[i] = fmaxf(sw[i], sw[i+s]); sh[i] = fmaxf(sh[i], sh[i+s]); }
        __syncthreads();
    }
    if (i == 0) { g_tbw[b] = sw[0]; g_tbh[b] = sh[0]; }
}

// ---------------- pair attr keys + fused pass-1 hist (smem-privatized) ----------------
__global__ void k_keys() {
    __shared__ unsigned shr[256], shc[256];
    int t = threadIdx.x;
    if (t < 256) { shr[t] = 0u; shc[t] = 0u; }
    __syncthreads();
    int p = blockIdx.x*256 + t;
    int b = blockIdx.y;
    if (p < NPAIR) {
        int i = p / 511, r = p % 511;
        int j = r + (r >= i ? 1 : 0);
        float cys = g_cy[b*NN+i], cyd = g_cy[b*NN+j];
        float cxs = g_cx[b*NN+i], cxd = g_cx[b*NN+j];
        float dr = (cys - cyd) * 5.0f / g_tbh[b];
        float dc = (cxs - cxd) * 5.0f / g_tbw[b];
        float vr = expf(-(dr*dr));
        float vc = expf(-(dc*dc));
        unsigned long long kr = (((unsigned long long)(~__float_as_uint(vr))) << 32) | (unsigned)p;
        unsigned long long kc = (((unsigned long long)(~__float_as_uint(vc))) << 32) | (unsigned)p;
        g_keys[b][p]     = kr;
        g_keys[4 + b][p] = kc;
        atomicAdd(&shr[(unsigned)(kr >> 56)], 1u);
        atomicAdd(&shc[(unsigned)(kc >> 56)], 1u);
    }
    __syncthreads();
    if (t < 256) {
        if (shr[t]) atomicAdd(&g_hist[b][t], shr[t]);
        if (shc[t]) atomicAdd(&g_hist[4 + b][t], shc[t]);
    }
}

// ---------------- radix select (8-bit digits) ----------------
__global__ void k_hist(int shift) {     // candidate-array version
    __shared__ unsigned sh[256];
    int seg = blockIdx.y;
    if (threadIdx.x < 256) sh[threadIdx.x] = 0u;
    __syncthreads();
    unsigned long long pref = g_prefix[seg];
    int n = g_ncand[seg];
    for (int idx = blockIdx.x*blockDim.x + threadIdx.x; idx < n; idx += gridDim.x*blockDim.x) {
        unsigned long long k = g_cand[seg][idx];
        if ((((k ^ pref) >> shift) >> 8) == 0ULL)
            atomicAdd(&sh[(unsigned)(k >> shift) & 255u], 1u);
    }
    __syncthreads();
    if (threadIdx.x < 256 && sh[threadIdx.x])
        atomicAdd(&g_hist[seg][threadIdx.x], sh[threadIdx.x]);
}

__global__ void k_scan(int shift) {
    int seg = threadIdx.x;
    if (seg >= 8) return;
    int need = g_kneed[seg];
    unsigned long long pref = g_prefix[seg];
    int cum = 0, chosen = 255, newneed = need;
    bool done = false;
    for (int bin = 0; bin < 256; bin++) {
        int c = (int)g_hist[seg][bin];
        g_hist[seg][bin] = 0u;
        if (!done && cum + c >= need) { chosen = bin; newneed = need - cum; done = true; }
        cum += c;
    }
    g_prefix[seg] = pref | ((unsigned long long)chosen << shift);
    g_kneed[seg] = newneed;
}

// ---------------- compact: emit sure keys (byte1 < b1), collect byte1 == b1 ----------------
__global__ void k_compact() {
    int seg = blockIdx.y;
    unsigned b1 = (unsigned)(g_prefix[seg] >> 56);
    for (int idx = blockIdx.x*blockDim.x + threadIdx.x; idx < NPAIR; idx += gridDim.x*blockDim.x) {
        unsigned long long k = g_keys[seg][idx];
        unsigned top = (unsigned)(k >> 56);
        if (top < b1) {
            emit_edge(seg, k);
        } else if (top == b1) {
            int pos = atomicAdd(&g_ncand[seg], 1);
            g_cand[seg][pos] = k;
        }
    }
}

// ---------------- final emit over candidates ----------------
__global__ void k_emitc() {
    int seg = blockIdx.y;
    unsigned long long pref = g_prefix[seg];
    int n = g_ncand[seg];
    for (int idx = blockIdx.x*blockDim.x + threadIdx.x; idx < n; idx += gridDim.x*blockDim.x) {
        unsigned long long k = g_cand[seg][idx];
        if (k <= pref) emit_edge(seg, k);
    }
}

// ---------------- ROI align 2x2 -> split bf16 ----------------
__global__ void k_roi(const float* __restrict__ boxes) {
    int n = blockIdx.x, c = threadIdx.x;
    int b = n >> 9;
    float x1 = boxes[n*4+0], y1 = boxes[n*4+1], x2 = boxes[n*4+2], y2 = boxes[n*4+3];
    float bw = (x2 - x1) / 2.0f, bh = (y2 - y1) / 2.0f;
    const float* base = g_dec + (size_t)b * HH * WWW * CO;
#pragma unroll
    for (int p = 0; p < 4; p++) {
        float py = y1 + (0.5f + (float)(p >> 1)) * bh;
        float px = x1 + (0.5f + (float)(p & 1)) * bw;
        py = fminf(fmaxf(py, 0.f), 47.f);
        px = fminf(fmaxf(px, 0.f), 47.f);
        int y0 = (int)floorf(py), x0 = (int)floorf(px);
        int y1i = min(y0 + 1, 47), x1i = min(x0 + 1, 47);
        float wy = py - (float)y0, wx = px - (float)x0;
        float f00 = base[(y0*48 + x0 )*CO + c];
        float f01 = base[(y0*48 + x1i)*CO + c];
        float f10 = base[(y1i*48 + x0 )*CO + c];
        float f11 = base[(y1i*48 + x1i)*CO + c];
        float v = f00*(1.f-wy)*(1.f-wx) + f01*(1.f-wy)*wx + f10*wy*(1.f-wx) + f11*wy*wx;
        __nv_bfloat16 h, l; split_bf16(v, h, l);
        g_cnnh[(size_t)n*1024 + p*256 + c] = h;
        g_cnnl[(size_t)n*1024 + p*256 + c] = l;
    }
}

// ---------------- GCN aggregation scatter ----------------
__global__ void k_agg() {
    int e = blockIdx.x, ty = blockIdx.y;
    int src = g_esrc[ty][e], dst = g_edst[ty][e];
    float norm = rsqrtf(g_deg[ty][src]) * g_ew[ty][e] * rsqrtf(g_deg[ty][dst]);
    const float* xs = g_xw[ty] + (size_t)src * GOUT;
    float* fd = g_feat[ty] + (size_t)dst * GOUT;
    for (int j = threadIdx.x; j < GOUT; j += blockDim.x)
        atomicAdd(&fd[j], norm * xs[j]);
}

__global__ void k_final(const float* __restrict__ bg0, const float* __restrict__ bg1) {
    int i = blockIdx.x*blockDim.x + threadIdx.x;
    if (i < 2*BN*GOUT) {
        int ty = i / (BN*GOUT);
        int r = i % (BN*GOUT);
        int j = r % GOUT;
        float bv = ty ? bg1[j] : bg0[j];
        float* f = (float*)g_feat;
        f[i] = fmaxf(f[i] + bv, 0.f);
    }
}

// ---------------- fp32 SGEMM 64x64x16 (classifiers) ----------------
template<int EPI>
__global__ void __launch_bounds__(256) k_sgemm(const float* __restrict__ A,
                                               const float* __restrict__ B,
                                               float* __restrict__ C,
                                               const float* __restrict__ bias,
                                               int M, int N, int K, int ldb, int ldc) {
    __shared__ __align__(16) float sA[16*68];
    __shared__ __align__(16) float sB[16*64];
    int t = threadIdx.x;
    int tx = t & 15, ty = t >> 4;
    int m0 = blockIdx.y * 64, n0 = blockIdx.x * 64;
    float acc[4][4];
#pragma unroll
    for (int i = 0; i < 4; i++)
#pragma unroll
        for (int j = 0; j < 4; j++) acc[i][j] = 0.f;

    int arow = t >> 2, acol = (t & 3) * 4;
    int brow = t >> 4, bcol = (t & 15) * 4;

    for (int k0 = 0; k0 < K; k0 += 16) {
        float4 av = *(const float4*)&A[(size_t)(m0 + arow) * K + k0 + acol];
        int kk = k0 + brow;
        int bn = n0 + bcol;
        float4 bv;
        if (bn + 3 < N) {
            bv = *(const float4*)&B[(size_t)kk * ldb + bn];
        } else {
            bv.x = (bn+0 < N) ? B[(size_t)kk*ldb + bn+0] : 0.f;
            bv.y = (bn+1 < N) ? B[(size_t)kk*ldb + bn+1] : 0.f;
            bv.z = (bn+2 < N) ? B[(size_t)kk*ldb + bn+2] : 0.f;
            bv.w = (bn+3 < N) ? B[(size_t)kk*ldb + bn+3] : 0.f;
        }
        __syncthreads();
        sA[(acol+0)*68 + arow] = av.x;
        sA[(acol+1)*68 + arow] = av.y;
        sA[(acol+2)*68 + arow] = av.z;
        sA[(acol+3)*68 + arow] = av.w;
        *(float4*)&sB[brow*64 + bcol] = bv;
        __syncthreads();
#pragma unroll
        for (int k2 = 0; k2 < 16; k2++) {
            float4 a = *(const float4*)&sA[k2*68 + ty*4];
            float4 b = *(const float4*)&sB[k2*64 + tx*4];
            acc[0][0] += a.x*b.x; acc[0][1] += a.x*b.y; acc[0][2] += a.x*b.z; acc[0][3] += a.x*b.w;
            acc[1][0] += a.y*b.x; acc[1][1] += a.y*b.y; acc[1][2] += a.y*b.z; acc[1][3] += a.y*b.w;
            acc[2][0] += a.z*b.x; acc[2][1] += a.z*b.y; acc[2][2] += a.z*b.z; acc[2][3] += a.z*b.w;
            acc[3][0] += a.w*b.x; acc[3][1] += a.w*b.y; acc[3][2] += a.w*b.z; acc[3][3] += a.w*b.w;
        }
    }
#pragma unroll
    for (int i = 0; i < 4; i++) {
        int m = m0 + ty*4 + i;
#pragma unroll
        for (int j = 0; j < 4; j++) {
            int n = n0 + tx*4 + j;
            if (n < N) {
                float v = acc[i][j];
                if (EPI == 1) v = fmaxf(v + bias[n], 0.f);
                else if (EPI == 2) { v = v + bias[n]; v = (v >= 0.f) ? v : 0.01f * v; }
                C[(size_t)m * ldc + n] = v;
            }
        }
    }
}

// ---------------- launch ----------------
extern "C" void kernel_launch(void* const* d_in, const int* in_sizes, int n_in,
                              void* d_out, int out_size) {
    const float* input  = (const float*)d_in[0];
    const float* boxes  = (const float*)d_in[1];
    const float* scales = (const float*)d_in[2];
    const float* pdls   = (const float*)d_in[3];
    const float* pdts   = (const float*)d_in[4];
    const float* W_dec  = (const float*)d_in[5];
    const float* b_dec  = (const float*)d_in[6];
    const float* W_box  = (const float*)d_in[7];
    const float* b_box  = (const float*)d_in[8];
    const float* W_cnn  = (const float*)d_in[9];
    const float* b_cnn  = (const float*)d_in[10];
    const float* W_grow = (const float*)d_in[11];
    const float* b_grow = (const float*)d_in[12];
    const float* W_gcol = (const float*)d_in[13];
    const float* b_gcol = (const float*)d_in[14];
    const float* W_rcls = (const float*)d_in[15];
    const float* b_rcls = (const float*)d_in[16];
    const float* W_ccls = (const float*)d_in[17];
    const float* b_ccls = (const float*)d_in[18];
    float* out = (float*)d_out;

    void *p1, *p2, *p3, *p4, *p5, *p6, *p7, *p8, *p9, *pa;
    cudaGetSymbolAddress(&p1, g_cnnh);  cudaGetSymbolAddress(&p2, g_cnnl);
    cudaGetSymbolAddress(&p3, g_fush);  cudaGetSymbolAddress(&p4, g_fusl);
    cudaGetSymbolAddress(&p5, g_wtch);  cudaGetSymbolAddress(&p6, g_wtcl);
    cudaGetSymbolAddress(&p7, g_wtgh);  cudaGetSymbolAddress(&p8, g_wtgl);
    cudaGetSymbolAddress(&p9, g_xw);    cudaGetSymbolAddress(&pa, g_feat);
    __nv_bfloat16* cnnh = (__nv_bfloat16*)p1;
    __nv_bfloat16* cnnl = (__nv_bfloat16*)p2;
    __nv_bfloat16* fush = (__nv_bfloat16*)p3;
    __nv_bfloat16* fusl = (__nv_bfloat16*)p4;
    __nv_bfloat16* wtch = (__nv_bfloat16*)p5;
    __nv_bfloat16* wtcl = (__nv_bfloat16*)p6;
    __nv_bfloat16* wtgh = (__nv_bfloat16*)p7;
    __nv_bfloat16* wtgl = (__nv_bfloat16*)p8;
    float* xw0 = (float*)p9;
    float* xw1 = xw0 + (size_t)BN*GOUT;
    float* f0  = (float*)pa;
    float* f1  = f0 + (size_t)BN*GOUT;

    cudaFuncSetAttribute(k_conv_wmma, cudaFuncAttributeMaxDynamicSharedMemorySize, CSMEM);
    cudaFuncSetAttribute(k_hgemm<0>, cudaFuncAttributeMaxDynamicSharedMemorySize, CSMEM);
    cudaFuncSetAttribute(k_hgemm<1>, cudaFuncAttributeMaxDynamicSharedMemorySize, CSMEM);

    k_init<<<8192, 256>>>();
    k_cvt_in<<<dim3(16, 3, BB*48), 256>>>(input);
    k_cvt_w<<<CO, 256>>>(W_dec);
    k_cvt_wcnn<<<512, 256>>>(W_cnn);
    k_cvt_wg<<<dim3(512, 2), 256>>>(W_grow, W_gcol);
    k_conv_wmma<<<dim3(2, 72), 512, CSMEM>>>(b_dec);
    k_boxfeat<<<BN, 256>>>(boxes, W_box, b_box);
    k_cxcy<<<BB, 512>>>(boxes, scales, pdls, pdts);
    k_keys<<<dim3(1022, 4), 256>>>();     // writes keys + pass-1 hist
    k_scan<<<1, 8>>>(56);
    k_compact<<<dim3(64, 8), 256>>>();    // emit sure keys, collect tie class
    for (int pass = 1; pass < 8; pass++) {
        int shift = 56 - 8*pass;
        k_hist<<<dim3(16, 8), 256>>>(shift);
        k_scan<<<1, 8>>>(shift);
    }
    k_emitc<<<dim3(16, 8), 256>>>();
    k_roi<<<BN, 256>>>(boxes);
    k_hgemm<1><<<dim3(4, 16), 512, CSMEM>>>(cnnh, cnnl, wtch, wtcl,
                                            nullptr, fush, fusl, b_cnn, 1024, FUS, 256);
    k_hgemm<0><<<dim3(4, 16), 512, CSMEM>>>(fush, fusl, wtgh, wtgl,
                                            xw0, nullptr, nullptr, nullptr, 768, 512, 0);
    k_hgemm<0><<<dim3(4, 16), 512, CSMEM>>>(fush, fusl, wtgh + (size_t)512*768, wtgl + (size_t)512*768,
                                            xw1, nullptr, nullptr, nullptr, 768, 512, 0);
    k_agg<<<dim3(ETOT, 2), 128>>>();
    k_final<<<(2*BN*GOUT + 255)/256, 256>>>(b_grow, b_gcol);
    k_sgemm<2><<<dim3(4, 32), 256>>>(f0, W_rcls, out, b_rcls, BN, RCLS, 512, RCLS, RCLS);
    k_sgemm<2><<<dim3(2, 32), 256>>>(f1, W_ccls, out + (size_t)BN*RCLS, b_ccls, BN, CCLS, 512, CCLS, CCLS);
}

// round 12
// speedup vs baseline: 1.0936x; 1.0936x over previous
#include <cuda_runtime.h>
#include <cuda_bf16.h>
#include <mma.h>
#include <cstdint>
#include <math.h>

using namespace nvcuda;

#define BB 4
#define NN 512
#define BN 2048
#define CIN 1024
#define HH 48
#define WWW 48
#define CO 256
#define NPAIR 261632          // 512*511
#define KEDGE 4096
#define ETOT (4*KEDGE + BN)   // 18432 edges per graph type (incl self loops)
#define GOUT 512
#define FUS 768
#define RCLS 228
#define CCLS 116

// HMMA tile kernels: 128x128 CTA tile, K-chunk 64, 512 threads.
#define CLD   72
#define CMAT  18432
#define CSTG  73728            // 4 mats (Ah|Al|Bh|Bl)
#define CSMEM (2*CSTG + 256)   // 147712

// ---------------- device scratch ----------------
__device__ __align__(1024) float g_dec[BB*HH*WWW*CO];
__device__ __align__(1024) __nv_bfloat16 g_inh[BB*HH*WWW*CIN];
__device__ __align__(1024) __nv_bfloat16 g_inl[BB*HH*WWW*CIN];
__device__ __align__(1024) __nv_bfloat16 g_wh[9*CO*CIN];
__device__ __align__(1024) __nv_bfloat16 g_wl[9*CO*CIN];
__device__ __align__(1024) __nv_bfloat16 g_cnnh[BN*1024], g_cnnl[BN*1024];
__device__ __align__(1024) __nv_bfloat16 g_fush[BN*FUS], g_fusl[BN*FUS];
__device__ __align__(1024) __nv_bfloat16 g_wtch[512*1024], g_wtcl[512*1024];
__device__ __align__(1024) __nv_bfloat16 g_wtgh[2][512*768], g_wtgl[2][512*768];
__device__ float g_cy[BB*NN], g_cx[BB*NN];
__device__ float g_tbh[BB], g_tbw[BB];
__device__ unsigned long long g_keys[8][NPAIR];
__device__ unsigned long long g_cand[8][NPAIR];
__device__ int g_ncand[8];
__device__ unsigned long long g_prefix[8];
__device__ int g_kneed[8];
__device__ unsigned int g_hist[8][256];
__device__ int g_ecount[8];
__device__ int   g_esrc[2][ETOT], g_edst[2][ETOT];
__device__ float g_ew[2][ETOT];
__device__ float g_deg[2][BN];
__device__ float g_xw[2][BN*GOUT];
__device__ float g_feat[2][BN*GOUT];

// ---------------- helpers ----------------
__device__ __forceinline__ uint32_t s2u(const void* p) {
    uint32_t a;
    asm("{ .reg .u64 t; cvta.to.shared.u64 t, %1; cvt.u32.u64 %0, t; }" : "=r"(a) : "l"(p));
    return a;
}
__device__ __forceinline__ void cp16(uint32_t dst, const void* src, int sz) {
    asm volatile("cp.async.cg.shared.global [%0], [%1], 16, %2;" :: "r"(dst), "l"(src), "r"(sz));
}
__device__ __forceinline__ void cp16f(uint32_t dst, const void* src) {
    asm volatile("cp.async.cg.shared.global [%0], [%1], 16;" :: "r"(dst), "l"(src));
}
__device__ __forceinline__ void cp_commit() { asm volatile("cp.async.commit_group;" ::: "memory"); }
__device__ __forceinline__ void cp_wait1() { asm volatile("cp.async.wait_group 1;" ::: "memory"); }
__device__ __forceinline__ void cp_wait0() { asm volatile("cp.async.wait_group 0;" ::: "memory"); }
__device__ __forceinline__ void split_bf16(float v, __nv_bfloat16& h, __nv_bfloat16& l) {
    h = __float2bfloat16(v);
    l = __float2bfloat16(v - __bfloat162float(h));
}

// emit one edge (shared by split + tie emit)
__device__ __forceinline__ void emit_edge(int seg, unsigned long long k) {
    int pos = atomicAdd(&g_ecount[seg], 1);
    if (pos < KEDGE) {
        int b = seg & 3, ty = seg >> 2;
        unsigned p = (unsigned)k & 0xFFFFFFFFu;
        int i = p / 511, r = p % 511;
        int j = r + (r >= i ? 1 : 0);
        float v = __uint_as_float(~(unsigned)(k >> 32));
        int slot = b*KEDGE + pos;
        int dst = b*NN + j;
        g_esrc[ty][slot] = b*NN + i;
        g_edst[ty][slot] = dst;
        g_ew[ty][slot] = v;
        atomicAdd(&g_deg[ty][dst], v);
    }
}

// ---------------- init ----------------
__global__ void k_init() {
    int t = blockIdx.x * blockDim.x + threadIdx.x;
    if (t < 8) { g_prefix[t] = 0ULL; g_kneed[t] = KEDGE; g_ecount[t] = 0; g_ncand[t] = 0; }
    if (t < 8*256) ((unsigned*)g_hist)[t] = 0u;
    if (t < 2*BN) {
        int ty = t / BN, i = t % BN;
        g_deg[ty][i] = 1.f;             // self loop weight
        g_esrc[ty][4*KEDGE + i] = i;
        g_edst[ty][4*KEDGE + i] = i;
        g_ew[ty][4*KEDGE + i] = 1.f;
    }
    if (t < 2*BN*GOUT) ((float*)g_feat)[t] = 0.f;
}

// ---------------- input NCHW fp32 -> NHWC split bf16 ----------------
__global__ void __launch_bounds__(256) k_cvt_in(const float* __restrict__ in) {
    __shared__ float sT[64][17];
    int ci0 = blockIdx.x * 64, x0 = blockIdx.y * 16;
    int by = blockIdx.z; int b = by / 48, y = by % 48;
    int t = threadIdx.x;
    int lx = t & 15, lc = t >> 4;
    const float* src = in + (size_t)b * CIN * 2304 + (size_t)y * 48 + x0;
#pragma unroll
    for (int j = 0; j < 4; j++)
        sT[lc + 16*j][lx] = src[(size_t)(ci0 + lc + 16*j) * 2304 + lx];
    __syncthreads();
    int wc = t & 63, wx = t >> 6;
#pragma unroll
    for (int j = 0; j < 4; j++) {
        float v = sT[wc][wx + 4*j];
        __nv_bfloat16 h, l; split_bf16(v, h, l);
        size_t o = ((size_t)(b*2304 + y*48 + x0 + wx + 4*j)) * 1024 + ci0 + wc;
        g_inh[o] = h; g_inl[o] = l;
    }
}

// ---------------- conv weights -> [tap][co][ci] split bf16 ----------------
__global__ void k_cvt_w(const float* __restrict__ W) {
    int co = blockIdx.x;
    for (int ci = threadIdx.x; ci < 1024; ci += 256) {
        const float* wp = W + ((size_t)co * 1024 + ci) * 9;
#pragma unroll
        for (int tap = 0; tap < 9; tap++) {
            __nv_bfloat16 h, l; split_bf16(wp[tap], h, l);
            size_t o = ((size_t)(tap*256 + co)) * 1024 + ci;
            g_wh[o] = h; g_wl[o] = l;
        }
    }
}

// ---------------- W_cnn -> [n][p*256+c] split bf16 (perm folded) ----------------
__global__ void k_cvt_wcnn(const float* __restrict__ W) {
    int n = blockIdx.x;
    for (int kk = threadIdx.x; kk < 1024; kk += 256) {
        int p = kk >> 8, c = kk & 255;
        float v = W[(size_t)(c*4 + p) * 512 + n];
        __nv_bfloat16 h, l; split_bf16(v, h, l);
        g_wtch[(size_t)n*1024 + kk] = h;
        g_wtcl[(size_t)n*1024 + kk] = l;
    }
}

// ---------------- W_grow/W_gcol -> [n][k] split bf16 ----------------
__global__ void k_cvt_wg(const float* __restrict__ W0, const float* __restrict__ W1) {
    int n = blockIdx.x, ty = blockIdx.y;
    const float* W = ty ? W1 : W0;
    for (int k = threadIdx.x; k < 768; k += 256) {
        __nv_bfloat16 h, l; split_bf16(W[(size_t)k * 512 + n], h, l);
        g_wtgh[ty][(size_t)n*768 + k] = h;
        g_wtgl[ty][(size_t)n*768 + k] = l;
    }
}

// ---------------- conv as 9 shifted GEMMs, HMMA split-bf16, 512 thr ----------------
// grid (2, 72): x = co-half (128 co), y = M-tile of 128 pixels.
__global__ void __launch_bounds__(512, 1) k_conv_wmma(const float* __restrict__ bias) {
    extern __shared__ char dsm_raw[];
    uint32_t raw = s2u(dsm_raw);
    uint32_t pad = (128u - (raw & 127u)) & 127u;
    char* sp = dsm_raw + pad;
    uint32_t spu = raw + pad;

    int t = threadIdx.x, wid = t >> 5;
    int co0 = blockIdx.x * 128;
    int tileM = blockIdx.y;
    int b = tileM / 18, loc0 = (tileM % 18) * 128;
    int wm = wid & 3, wn = wid >> 2;   // warp tile 32x32

    const __nv_bfloat16* inh_b = g_inh + (size_t)b * 2304 * 1024;
    const __nv_bfloat16* inl_b = g_inl + (size_t)b * 2304 * 1024;

    int rowL[2], qL[2], pyL[2], pxL[2];
#pragma unroll
    for (int i = 0; i < 2; i++) {
        int idx = t + 512*i;
        rowL[i] = idx >> 3; qL[i] = idx & 7;
        int l = loc0 + rowL[i];
        pyL[i] = l / 48; pxL[i] = l % 48;
    }

    wmma::fragment<wmma::accumulator, 16, 16, 16, float> acc[2][2];
#pragma unroll
    for (int i = 0; i < 2; i++)
#pragma unroll
        for (int j = 0; j < 2; j++) wmma::fill_fragment(acc[i][j], 0.f);

#define ISSUE_CHUNK(c) do {                                                       \
        int tap_ = (c) >> 4, ci0_ = ((c) & 15) << 6;                              \
        int dy_ = tap_ / 3 - 1, dx_ = tap_ % 3 - 1;                               \
        uint32_t sb_ = spu + ((c) & 1) * CSTG;                                    \
        _Pragma("unroll")                                                         \
        for (int i = 0; i < 2; i++) {                                             \
            int row_ = rowL[i], q_ = qL[i];                                       \
            uint32_t so_ = (uint32_t)(row_*(CLD*2) + q_*16);                      \
            int ys_ = pyL[i] + dy_, xs_ = pxL[i] + dx_;                           \
            bool ok_ = ((unsigned)ys_ < 48u) & ((unsigned)xs_ < 48u);             \
            size_t go_ = ok_ ? ((size_t)(ys_*48 + xs_)*1024 + ci0_ + q_*8) : 0;   \
            int sz_ = ok_ ? 16 : 0;                                               \
            cp16(sb_ + so_,          inh_b + go_, sz_);                           \
            cp16(sb_ + CMAT + so_,   inl_b + go_, sz_);                           \
            size_t wo_ = (size_t)(tap_*256 + co0 + row_)*1024 + ci0_ + q_*8;      \
            cp16f(sb_ + 2*CMAT + so_, g_wh + wo_);                                \
            cp16f(sb_ + 3*CMAT + so_, g_wl + wo_);                                \
        }                                                                         \
    } while (0)

    ISSUE_CHUNK(0);
    cp_commit();

    for (int c = 0; c < 144; c++) {
        if (c + 1 < 144) { ISSUE_CHUNK(c + 1); cp_commit(); cp_wait1(); }
        else             { cp_wait0(); }
        __syncthreads();
        const char* sb = sp + (c & 1) * CSTG;
        const __nv_bfloat16* Ah = (const __nv_bfloat16*)(sb);
        const __nv_bfloat16* Al = (const __nv_bfloat16*)(sb + CMAT);
        const __nv_bfloat16* Bh = (const __nv_bfloat16*)(sb + 2*CMAT);
        const __nv_bfloat16* Bl = (const __nv_bfloat16*)(sb + 3*CMAT);
#pragma unroll
        for (int kk = 0; kk < 64; kk += 16) {
            wmma::fragment<wmma::matrix_a, 16, 16, 16, __nv_bfloat16, wmma::row_major> ah[2], al[2];
            wmma::fragment<wmma::matrix_b, 16, 16, 16, __nv_bfloat16, wmma::col_major> bh[2], bl[2];
#pragma unroll
            for (int i = 0; i < 2; i++) {
                wmma::load_matrix_sync(ah[i], Ah + (wm*32 + i*16)*CLD + kk, CLD);
                wmma::load_matrix_sync(al[i], Al + (wm*32 + i*16)*CLD + kk, CLD);
            }
#pragma unroll
            for (int j = 0; j < 2; j++) {
                wmma::load_matrix_sync(bh[j], Bh + (wn*32 + j*16)*CLD + kk, CLD);
                wmma::load_matrix_sync(bl[j], Bl + (wn*32 + j*16)*CLD + kk, CLD);
            }
#pragma unroll
            for (int i = 0; i < 2; i++)
#pragma unroll
                for (int j = 0; j < 2; j++) {
                    wmma::mma_sync(acc[i][j], ah[i], bh[j], acc[i][j]);
                    wmma::mma_sync(acc[i][j], al[i], bh[j], acc[i][j]);
                    wmma::mma_sync(acc[i][j], ah[i], bl[j], acc[i][j]);
                }
        }
        __syncthreads();
    }
#undef ISSUE_CHUNK

    float* sE = (float*)sp;
#pragma unroll
    for (int i = 0; i < 2; i++)
#pragma unroll
        for (int j = 0; j < 2; j++)
            wmma::store_matrix_sync(sE + (wm*32 + i*16)*128 + wn*32 + j*16,
                                    acc[i][j], 128, wmma::mem_row_major);
    __syncthreads();
#pragma unroll
    for (int r = 0; r < 8; r++) {
        int idx = t + 512*r;
        int row = idx >> 5, col = (idx & 31) * 4;
        float4 v = *(const float4*)&sE[row*128 + col];
        v.x = fmaxf(v.x + bias[co0+col+0], 0.f);
        v.y = fmaxf(v.y + bias[co0+col+1], 0.f);
        v.z = fmaxf(v.z + bias[co0+col+2], 0.f);
        v.w = fmaxf(v.w + bias[co0+col+3], 0.f);
        int pix = b*2304 + loc0 + row;
        *(float4*)&g_dec[(size_t)pix*256 + co0 + col] = v;
    }
}

// ---------------- split-bf16 HMMA GEMM: C[M,N] = A[M,K] * B[N,K]^T ----------------
template<int EPI>
__global__ void __launch_bounds__(512, 1) k_hgemm(const __nv_bfloat16* __restrict__ Agh,
                                                  const __nv_bfloat16* __restrict__ Agl,
                                                  const __nv_bfloat16* __restrict__ Bgh,
                                                  const __nv_bfloat16* __restrict__ Bgl,
                                                  float* C, __nv_bfloat16* Ch, __nv_bfloat16* Cl,
                                                  const float* __restrict__ bias,
                                                  int K, int ldc, int colofs) {
    extern __shared__ char dsm_raw[];
    uint32_t raw = s2u(dsm_raw);
    uint32_t pad = (128u - (raw & 127u)) & 127u;
    char* sp = dsm_raw + pad;
    uint32_t spu = raw + pad;

    int t = threadIdx.x, wid = t >> 5;
    int n0 = blockIdx.x * 128, m0 = blockIdx.y * 128;
    int wm = wid & 3, wn = wid >> 2;

    int rowL[2], qL[2];
#pragma unroll
    for (int i = 0; i < 2; i++) {
        int idx = t + 512*i;
        rowL[i] = idx >> 3; qL[i] = idx & 7;
    }

    wmma::fragment<wmma::accumulator, 16, 16, 16, float> acc[2][2];
#pragma unroll
    for (int i = 0; i < 2; i++)
#pragma unroll
        for (int j = 0; j < 2; j++) wmma::fill_fragment(acc[i][j], 0.f);

    int nch = K >> 6;
#define ISSUE_G(c) do {                                                          \
        int k0_ = (c) << 6;                                                      \
        uint32_t sb_ = spu + ((c) & 1) * CSTG;                                   \
        _Pragma("unroll")                                                        \
        for (int i = 0; i < 2; i++) {                                            \
            int row_ = rowL[i], q_ = qL[i];                                      \
            uint32_t so_ = (uint32_t)(row_*(CLD*2) + q_*16);                     \
            size_t ao_ = (size_t)(m0 + row_)*K + k0_ + q_*8;                     \
            cp16f(sb_ + so_,        Agh + ao_);                                  \
            cp16f(sb_ + CMAT + so_, Agl + ao_);                                  \
            size_t bo_ = (size_t)(n0 + row_)*K + k0_ + q_*8;                     \
            cp16f(sb_ + 2*CMAT + so_, Bgh + bo_);                                \
            cp16f(sb_ + 3*CMAT + so_, Bgl + bo_);                                \
        }                                                                        \
    } while (0)

    ISSUE_G(0);
    cp_commit();
    for (int c = 0; c < nch; c++) {
        if (c + 1 < nch) { ISSUE_G(c + 1); cp_commit(); cp_wait1(); }
        else             { cp_wait0(); }
        __syncthreads();
        const char* sb = sp + (c & 1) * CSTG;
        const __nv_bfloat16* Ah = (const __nv_bfloat16*)(sb);
        const __nv_bfloat16* Al = (const __nv_bfloat16*)(sb + CMAT);
        const __nv_bfloat16* Bh = (const __nv_bfloat16*)(sb + 2*CMAT);
        const __nv_bfloat16* Bl = (const __nv_bfloat16*)(sb + 3*CMAT);
#pragma unroll
        for (int kk = 0; kk < 64; kk += 16) {
            wmma::fragment<wmma::matrix_a, 16, 16, 16, __nv_bfloat16, wmma::row_major> ah[2], al[2];
            wmma::fragment<wmma::matrix_b, 16, 16, 16, __nv_bfloat16, wmma::col_major> bh[2], bl[2];
#pragma unroll
            for (int i = 0; i < 2; i++) {
                wmma::load_matrix_sync(ah[i], Ah + (wm*32 + i*16)*CLD + kk, CLD);
                wmma::load_matrix_sync(al[i], Al + (wm*32 + i*16)*CLD + kk, CLD);
            }
#pragma unroll
            for (int j = 0; j < 2; j++) {
                wmma::load_matrix_sync(bh[j], Bh + (wn*32 + j*16)*CLD + kk, CLD);
                wmma::load_matrix_sync(bl[j], Bl + (wn*32 + j*16)*CLD + kk, CLD);
            }
#pragma unroll
            for (int i = 0; i < 2; i++)
#pragma unroll
                for (int j = 0; j < 2; j++) {
                    wmma::mma_sync(acc[i][j], ah[i], bh[j], acc[i][j]);
                    wmma::mma_sync(acc[i][j], al[i], bh[j], acc[i][j]);
                    wmma::mma_sync(acc[i][j], ah[i], bl[j], acc[i][j]);
                }
        }
        __syncthreads();
    }
#undef ISSUE_G

    float* sE = (float*)sp;
#pragma unroll
    for (int i = 0; i < 2; i++)
#pragma unroll
        for (int j = 0; j < 2; j++)
            wmma::store_matrix_sync(sE + (wm*32 + i*16)*128 + wn*32 + j*16,
                                    acc[i][j], 128, wmma::mem_row_major);
    __syncthreads();
#pragma unroll
    for (int r = 0; r < 8; r++) {
        int idx = t + 512*r;
        int row = idx >> 5, col = (idx & 31) * 4;
        float4 v = *(const float4*)&sE[row*128 + col];
        if (EPI == 0) {
            *(float4*)&C[(size_t)(m0 + row)*ldc + n0 + col] = v;
        } else {
            v.x = fmaxf(v.x + bias[n0+col+0], 0.f);
            v.y = fmaxf(v.y + bias[n0+col+1], 0.f);
            v.z = fmaxf(v.z + bias[n0+col+2], 0.f);
            v.w = fmaxf(v.w + bias[n0+col+3], 0.f);
            __nv_bfloat16 h0,l0,h1,l1,h2,l2,h3,l3;
            split_bf16(v.x,h0,l0); split_bf16(v.y,h1,l1);
            split_bf16(v.z,h2,l2); split_bf16(v.w,h3,l3);
            size_t o = (size_t)(m0 + row)*ldc + colofs + n0 + col;
            __nv_bfloat162* ph = (__nv_bfloat162*)&Ch[o];
            __nv_bfloat162* pl = (__nv_bfloat162*)&Cl[o];
            ph[0] = __nv_bfloat162(h0, h1); ph[1] = __nv_bfloat162(h2, h3);
            pl[0] = __nv_bfloat162(l0, l1); pl[1] = __nv_bfloat162(l2, l3);
        }
    }
}

// ---------------- box feature MLP -> fusion split bf16 ----------------
__global__ void k_boxfeat(const float* __restrict__ boxes,
                          const float* __restrict__ Wb, const float* __restrict__ bb) {
    int n = blockIdx.x, co = threadIdx.x;
    float f0 = boxes[n*4+0], f1 = boxes[n*4+1], f2 = boxes[n*4+2], f3 = boxes[n*4+3];
    float cx = (f0 + f2) / 2.0f, cy = (f1 + f3) / 2.0f;
    float b0 = cx / 48.0f, b1 = cy / 48.0f;
    float b2 = (f2 - f0) / 48.0f, b3 = (f3 - f1) / 48.0f;
    float v = bb[co] + b0*Wb[co] + b1*Wb[256+co] + b2*Wb[512+co] + b3*Wb[768+co];
    v = fmaxf(v, 0.f);
    __nv_bfloat16 h, l; split_bf16(v, h, l);
    g_fush[(size_t)n*FUS + co] = h;
    g_fusl[(size_t)n*FUS + co] = l;
}

// ---------------- cx/cy + table extents ----------------
__global__ void k_cxcy(const float* __restrict__ boxes, const float* __restrict__ scales,
                       const float* __restrict__ pdls, const float* __restrict__ pdts) {
    int b = blockIdx.x, i = threadIdx.x;
    float sc = scales[b], pl = pdls[b], pt = pdts[b];
    const float* bx = boxes + ((size_t)b*NN + i)*4;
    float o0 = (bx[0]-pl)/sc, o1 = (bx[1]-pt)/sc, o2 = (bx[2]-pl)/sc, o3 = (bx[3]-pt)/sc;
    g_cx[b*NN+i] = (o0 + o2) * 0.5f;
    g_cy[b*NN+i] = (o1 + o3) * 0.5f;
    __shared__ float sw[512], sh[512];
    sw[i] = fmaxf(o0, o2); sh[i] = fmaxf(o1, o3);
    __syncthreads();
    for (int s = 256; s > 0; s >>= 1) {
        if (i < s) { sw[i] = fmaxf(sw[i], sw[i+s]); sh[i] = fmaxf(sh[i], sh[i+s]); }
        __syncthreads();
    }
    if (i == 0) { g_tbw[b] = sw[0]; g_tbh[b] = sh[0]; }
}

// ---------------- pair attr keys + fused pass-1 hist (smem-privatized) ----------------
__global__ void k_keys() {
    __shared__ unsigned shr[256], shc[256];
    int t = threadIdx.x;
    if (t < 256) { shr[t] = 0u; shc[t] = 0u; }
    __syncthreads();
    int p = blockIdx.x*256 + t;
    int b = blockIdx.y;
    if (p < NPAIR) {
        int i = p / 511, r = p % 511;
        int j = r + (r >= i ? 1 : 0);
        float cys = g_cy[b*NN+i], cyd = g_cy[b*NN+j];
        float cxs = g_cx[b*NN+i], cxd = g_cx[b*NN+j];
        float dr = (cys - cyd) * 5.0f / g_tbh[b];
        float dc = (cxs - cxd) * 5.0f / g_tbw[b];
        float vr = expf(-(dr*dr));
        float vc = expf(-(dc*dc));
        unsigned long long kr = (((unsigned long long)(~__float_as_uint(vr))) << 32) | (unsigned)p;
        unsigned long long kc = (((unsigned long long)(~__float_as_uint(vc))) << 32) | (unsigned)p;
        g_keys[b][p]     = kr;
        g_keys[4 + b][p] = kc;
        atomicAdd(&shr[(unsigned)(kr >> 56)], 1u);
        atomicAdd(&shc[(unsigned)(kc >> 56)], 1u);
    }
    __syncthreads();
    if (t < 256) {
        if (shr[t]) atomicAdd(&g_hist[b][t], shr[t]);
        if (shc[t]) atomicAdd(&g_hist[4 + b][t], shc[t]);
    }
}

// ---------------- radix select: full-array hist (value bytes) ----------------
__global__ void k_hist(int shift) {
    __shared__ unsigned sh[256];
    int seg = blockIdx.y;
    if (threadIdx.x < 256) sh[threadIdx.x] = 0u;
    __syncthreads();
    unsigned long long pref = g_prefix[seg];
    for (int idx = blockIdx.x*blockDim.x + threadIdx.x; idx < NPAIR; idx += gridDim.x*blockDim.x) {
        unsigned long long k = g_keys[seg][idx];
        if ((((k ^ pref) >> shift) >> 8) == 0ULL)
            atomicAdd(&sh[(unsigned)(k >> shift) & 255u], 1u);
    }
    __syncthreads();
    if (threadIdx.x < 256 && sh[threadIdx.x])
        atomicAdd(&g_hist[seg][threadIdx.x], sh[threadIdx.x]);
}

// ---------------- tie-buffer hist (index bytes) ----------------
__global__ void k_histc(int shift) {
    __shared__ unsigned sh[256];
    int seg = blockIdx.y;
    if (threadIdx.x < 256) sh[threadIdx.x] = 0u;
    __syncthreads();
    unsigned long long pref = g_prefix[seg];
    int n = g_ncand[seg];
    for (int idx = blockIdx.x*blockDim.x + threadIdx.x; idx < n; idx += gridDim.x*blockDim.x) {
        unsigned long long k = g_cand[seg][idx];
        if ((((k ^ pref) >> shift) >> 8) == 0ULL)
            atomicAdd(&sh[(unsigned)(k >> shift) & 255u], 1u);
    }
    __syncthreads();
    if (threadIdx.x < 256 && sh[threadIdx.x])
        atomicAdd(&g_hist[seg][threadIdx.x], sh[threadIdx.x]);
}

__global__ void k_scan(int shift) {
    int seg = threadIdx.x;
    if (seg >= 8) return;
    int need = g_kneed[seg];
    unsigned long long pref = g_prefix[seg];
    int cum = 0, chosen = 255, newneed = need;
    bool done = false;
    for (int bin = 0; bin < 256; bin++) {
        int c = (int)g_hist[seg][bin];
        g_hist[seg][bin] = 0u;
        if (!done && cum + c >= need) { chosen = bin; newneed = need - cum; done = true; }
        cum += c;
    }
    g_prefix[seg] = pref | ((unsigned long long)chosen << shift);
    g_kneed[seg] = newneed;
}

// ---------------- split: emit value_top32 < boundary, collect exact-value ties ----------------
__global__ void k_split() {
    int seg = blockIdx.y;
    unsigned bound = (unsigned)(g_prefix[seg] >> 32);
    for (int idx = blockIdx.x*blockDim.x + threadIdx.x; idx < NPAIR; idx += gridDim.x*blockDim.x) {
        unsigned long long k = g_keys[seg][idx];
        unsigned top = (unsigned)(k >> 32);
        if (top < bound) {
            emit_edge(seg, k);
        } else if (top == bound) {
            int pos = atomicAdd(&g_ncand[seg], 1);
            g_cand[seg][pos] = k;
        }
    }
}

// ---------------- final emit over ties ----------------
__global__ void k_emitc() {
    int seg = blockIdx.y;
    unsigned long long pref = g_prefix[seg];
    int n = g_ncand[seg];
    for (int idx = blockIdx.x*blockDim.x + threadIdx.x; idx < n; idx += gridDim.x*blockDim.x) {
        unsigned long long k = g_cand[seg][idx];
        if (k <= pref) emit_edge(seg, k);
    }
}

// ---------------- ROI align 2x2 -> split bf16 ----------------
__global__ void k_roi(const float* __restrict__ boxes) {
    int n = blockIdx.x, c = threadIdx.x;
    int b = n >> 9;
    float x1 = boxes[n*4+0], y1 = boxes[n*4+1], x2 = boxes[n*4+2], y2 = boxes[n*4+3];
    float bw = (x2 - x1) / 2.0f, bh = (y2 - y1) / 2.0f;
    const float* base = g_dec + (size_t)b * HH * WWW * CO;
#pragma unroll
    for (int p = 0; p < 4; p++) {
        float py = y1 + (0.5f + (float)(p >> 1)) * bh;
        float px = x1 + (0.5f + (float)(p & 1)) * bw;
        py = fminf(fmaxf(py, 0.f), 47.f);
        px = fminf(fmaxf(px, 0.f), 47.f);
        int y0 = (int)floorf(py), x0 = (int)floorf(px);
        int y1i = min(y0 + 1, 47), x1i = min(x0 + 1, 47);
        float wy = py - (float)y0, wx = px - (float)x0;
        float f00 = base[(y0*48 + x0 )*CO + c];
        float f01 = base[(y0*48 + x1i)*CO + c];
        float f10 = base[(y1i*48 + x0 )*CO + c];
        float f11 = base[(y1i*48 + x1i)*CO + c];
        float v = f00*(1.f-wy)*(1.f-wx) + f01*(1.f-wy)*wx + f10*wy*(1.f-wx) + f11*wy*wx;
        __nv_bfloat16 h, l; split_bf16(v, h, l);
        g_cnnh[(size_t)n*1024 + p*256 + c] = h;
        g_cnnl[(size_t)n*1024 + p*256 + c] = l;
    }
}

// ---------------- GCN aggregation scatter ----------------
__global__ void k_agg() {
    int e = blockIdx.x, ty = blockIdx.y;
    int src = g_esrc[ty][e], dst = g_edst[ty][e];
    float norm = rsqrtf(g_deg[ty][src]) * g_ew[ty][e] * rsqrtf(g_deg[ty][dst]);
    const float* xs = g_xw[ty] + (size_t)src * GOUT;
    float* fd = g_feat[ty] + (size_t)dst * GOUT;
    for (int j = threadIdx.x; j < GOUT; j += blockDim.x)
        atomicAdd(&fd[j], norm * xs[j]);
}

__global__ void k_final(const float* __restrict__ bg0, const float* __restrict__ bg1) {
    int i = blockIdx.x*blockDim.x + threadIdx.x;
    if (i < 2*BN*GOUT) {
        int ty = i / (BN*GOUT);
        int r = i % (BN*GOUT);
        int j = r % GOUT;
        float bv = ty ? bg1[j] : bg0[j];
        float* f = (float*)g_feat;
        f[i] = fmaxf(f[i] + bv, 0.f);
    }
}

// ---------------- fp32 SGEMM 64x64x16 (classifiers) ----------------
template<int EPI>
__global__ void __launch_bounds__(256) k_sgemm(const float* __restrict__ A,
                                               const float* __restrict__ B,
                                               float* __restrict__ C,
                                               const float* __restrict__ bias,
                                               int M, int N, int K, int ldb, int ldc) {
    __shared__ __align__(16) float sA[16*68];
    __shared__ __align__(16) float sB[16*64];
    int t = threadIdx.x;
    int tx = t & 15, ty = t >> 4;
    int m0 = blockIdx.y * 64, n0 = blockIdx.x * 64;
    float acc[4][4];
#pragma unroll
    for (int i = 0; i < 4; i++)
#pragma unroll
        for (int j = 0; j < 4; j++) acc[i][j] = 0.f;

    int arow = t >> 2, acol = (t & 3) * 4;
    int brow = t >> 4, bcol = (t & 15) * 4;

    for (int k0 = 0; k0 < K; k0 += 16) {
        float4 av = *(const float4*)&A[(size_t)(m0 + arow) * K + k0 + acol];
        int kk = k0 + brow;
        int bn = n0 + bcol;
        float4 bv;
        if (bn + 3 < N) {
            bv = *(const float4*)&B[(size_t)kk * ldb + bn];
        } else {
            bv.x = (bn+0 < N) ? B[(size_t)kk*ldb + bn+0] : 0.f;
            bv.y = (bn+1 < N) ? B[(size_t)kk*ldb + bn+1] : 0.f;
            bv.z = (bn+2 < N) ? B[(size_t)kk*ldb + bn+2] : 0.f;
            bv.w = (bn+3 < N) ? B[(size_t)kk*ldb + bn+3] : 0.f;
        }
        __syncthreads();
        sA[(acol+0)*68 + arow] = av.x;
        sA[(acol+1)*68 + arow] = av.y;
        sA[(acol+2)*68 + arow] = av.z;
        sA[(acol+3)*68 + arow] = av.w;
        *(float4*)&sB[brow*64 + bcol] = bv;
        __syncthreads();
#pragma unroll
        for (int k2 = 0; k2 < 16; k2++) {
            float4 a = *(const float4*)&sA[k2*68 + ty*4];
            float4 b = *(const float4*)&sB[k2*64 + tx*4];
            acc[0][0] += a.x*b.x; acc[0][1] += a.x*b.y; acc[0][2] += a.x*b.z; acc[0][3] += a.x*b.w;
            acc[1][0] += a.y*b.x; acc[1][1] += a.y*b.y; acc[1][2] += a.y*b.z; acc[1][3] += a.y*b.w;
            acc[2][0] += a.z*b.x; acc[2][1] += a.z*b.y; acc[2][2] += a.z*b.z; acc[2][3] += a.z*b.w;
            acc[3][0] += a.w*b.x; acc[3][1] += a.w*b.y; acc[3][2] += a.w*b.z; acc[3][3] += a.w*b.w;
        }
    }
#pragma unroll
    for (int i = 0; i < 4; i++) {
        int m = m0 + ty*4 + i;
#pragma unroll
        for (int j = 0; j < 4; j++) {
            int n = n0 + tx*4 + j;
            if (n < N) {
                float v = acc[i][j];
                if (EPI == 1) v = fmaxf(v + bias[n], 0.f);
                else if (EPI == 2) { v = v + bias[n]; v = (v >= 0.f) ? v : 0.01f * v; }
                C[(size_t)m * ldc + n] = v;
            }
        }
    }
}

// ---------------- launch ----------------
extern "C" void kernel_launch(void* const* d_in, const int* in_sizes, int n_in,
                              void* d_out, int out_size) {
    const float* input  = (const float*)d_in[0];
    const float* boxes  = (const float*)d_in[1];
    const float* scales = (const float*)d_in[2];
    const float* pdls   = (const float*)d_in[3];
    const float* pdts   = (const float*)d_in[4];
    const float* W_dec  = (const float*)d_in[5];
    const float* b_dec  = (const float*)d_in[6];
    const float* W_box  = (const float*)d_in[7];
    const float* b_box  = (const float*)d_in[8];
    const float* W_cnn  = (const float*)d_in[9];
    const float* b_cnn  = (const float*)d_in[10];
    const float* W_grow = (const float*)d_in[11];
    const float* b_grow = (const float*)d_in[12];
    const float* W_gcol = (const float*)d_in[13];
    const float* b_gcol = (const float*)d_in[14];
    const float* W_rcls = (const float*)d_in[15];
    const float* b_rcls = (const float*)d_in[16];
    const float* W_ccls = (const float*)d_in[17];
    const float* b_ccls = (const float*)d_in[18];
    float* out = (float*)d_out;

    void *p1, *p2, *p3, *p4, *p5, *p6, *p7, *p8, *p9, *pa;
    cudaGetSymbolAddress(&p1, g_cnnh);  cudaGetSymbolAddress(&p2, g_cnnl);
    cudaGetSymbolAddress(&p3, g_fush);  cudaGetSymbolAddress(&p4, g_fusl);
    cudaGetSymbolAddress(&p5, g_wtch);  cudaGetSymbolAddress(&p6, g_wtcl);
    cudaGetSymbolAddress(&p7, g_wtgh);  cudaGetSymbolAddress(&p8, g_wtgl);
    cudaGetSymbolAddress(&p9, g_xw);    cudaGetSymbolAddress(&pa, g_feat);
    __nv_bfloat16* cnnh = (__nv_bfloat16*)p1;
    __nv_bfloat16* cnnl = (__nv_bfloat16*)p2;
    __nv_bfloat16* fush = (__nv_bfloat16*)p3;
    __nv_bfloat16* fusl = (__nv_bfloat16*)p4;
    __nv_bfloat16* wtch = (__nv_bfloat16*)p5;
    __nv_bfloat16* wtcl = (__nv_bfloat16*)p6;
    __nv_bfloat16* wtgh = (__nv_bfloat16*)p7;
    __nv_bfloat16* wtgl = (__nv_bfloat16*)p8;
    float* xw0 = (float*)p9;
    float* xw1 = xw0 + (size_t)BN*GOUT;
    float* f0  = (float*)pa;
    float* f1  = f0 + (size_t)BN*GOUT;

    cudaFuncSetAttribute(k_conv_wmma, cudaFuncAttributeMaxDynamicSharedMemorySize, CSMEM);
    cudaFuncSetAttribute(k_hgemm<0>, cudaFuncAttributeMaxDynamicSharedMemorySize, CSMEM);
    cudaFuncSetAttribute(k_hgemm<1>, cudaFuncAttributeMaxDynamicSharedMemorySize, CSMEM);

    k_init<<<8192, 256>>>();
    k_cvt_in<<<dim3(16, 3, BB*48), 256>>>(input);
    k_cvt_w<<<CO, 256>>>(W_dec);
    k_cvt_wcnn<<<512, 256>>>(W_cnn);
    k_cvt_wg<<<dim3(512, 2), 256>>>(W_grow, W_gcol);
    k_conv_wmma<<<dim3(2, 72), 512, CSMEM>>>(b_dec);
    k_boxfeat<<<BN, 256>>>(boxes, W_box, b_box);
    k_cxcy<<<BB, 512>>>(boxes, scales, pdls, pdts);
    // --- top-k select: value bytes (1 fused + 3 full passes), then tiny tie passes ---
    k_keys<<<dim3(1022, 4), 256>>>();       // keys + hist @56
    k_scan<<<1, 8>>>(56);
    k_hist<<<dim3(64, 8), 256>>>(48);  k_scan<<<1, 8>>>(48);
    k_hist<<<dim3(64, 8), 256>>>(40);  k_scan<<<1, 8>>>(40);
    k_hist<<<dim3(64, 8), 256>>>(32);  k_scan<<<1, 8>>>(32);
    k_split<<<dim3(64, 8), 256>>>();        // emit sure winners, collect exact-value ties
    k_histc<<<dim3(8, 8), 256>>>(16);  k_scan<<<1, 8>>>(16);
    k_histc<<<dim3(8, 8), 256>>>(8);   k_scan<<<1, 8>>>(8);
    k_histc<<<dim3(8, 8), 256>>>(0);   k_scan<<<1, 8>>>(0);
    k_emitc<<<dim3(8, 8), 256>>>();
    k_roi<<<BN, 256>>>(boxes);
    k_hgemm<1><<<dim3(4, 16), 512, CSMEM>>>(cnnh, cnnl, wtch, wtcl,
                                            nullptr, fush, fusl, b_cnn, 1024, FUS, 256);
    k_hgemm<0><<<dim3(4, 16), 512, CSMEM>>>(fush, fusl, wtgh, wtgl,
                                            xw0, nullptr, nullptr, nullptr, 768, 512, 0);
    k_hgemm<0><<<dim3(4, 16), 512, CSMEM>>>(fush, fusl, wtgh + (size_t)512*768, wtgl + (size_t)512*768,
                                            xw1, nullptr, nullptr, nullptr, 768, 512, 0);
    k_agg<<<dim3(ETOT, 2), 128>>>();
    k_final<<<(2*BN*GOUT + 255)/256, 256>>>(b_grow, b_gcol);
    k_sgemm<2><<<dim3(4, 32), 256>>>(f0, W_rcls, out, b_rcls, BN, RCLS, 512, RCLS, RCLS);
    k_sgemm<2><<<dim3(2, 32), 256>>>(f1, W_ccls, out + (size_t)BN*RCLS, b_ccls, BN, CCLS, 512, CCLS, CCLS);
}

// round 15
// speedup vs baseline: 1.1029x; 1.0085x over previous
#include <cuda_runtime.h>
#include <cuda_bf16.h>
#include <mma.h>
#include <cstdint>
#include <math.h>

using namespace nvcuda;

#define BB 4
#define NN 512
#define BN 2048
#define CIN 1024
#define HH 48
#define WWW 48
#define CO 256
#define NPAIR 261632          // 512*511
#define KEDGE 4096
#define ETOT (4*KEDGE + BN)   // 18432 edges per graph type (incl self loops)
#define GOUT 512
#define FUS 768
#define RCLS 228
#define CCLS 116

// HMMA tile kernels: 128x128 CTA tile, K-chunk 64, 512 threads.
#define CLD   72
#define CMAT  18432
#define CSTG  73728            // 4 mats (Ah|Al|Bh|Bl)
#define CSMEM (2*CSTG + 256)   // 147712

// ---------------- device scratch ----------------
__device__ __align__(1024) float g_dec[BB*HH*WWW*CO];
__device__ __align__(1024) __nv_bfloat16 g_inh[BB*HH*WWW*CIN];
__device__ __align__(1024) __nv_bfloat16 g_inl[BB*HH*WWW*CIN];
__device__ __align__(1024) __nv_bfloat16 g_wh[9*CO*CIN];
__device__ __align__(1024) __nv_bfloat16 g_wl[9*CO*CIN];
__device__ __align__(1024) __nv_bfloat16 g_cnnh[BN*1024], g_cnnl[BN*1024];
__device__ __align__(1024) __nv_bfloat16 g_fush[BN*FUS], g_fusl[BN*FUS];
__device__ __align__(1024) __nv_bfloat16 g_wtch[512*1024], g_wtcl[512*1024];
__device__ __align__(1024) __nv_bfloat16 g_wtgh[2][512*768], g_wtgl[2][512*768];
__device__ __align__(1024) __nv_bfloat16 g_wtrh[RCLS*512], g_wtrl[RCLS*512];
__device__ __align__(1024) __nv_bfloat16 g_wtcch[CCLS*512], g_wtccl[CCLS*512];
__device__ __align__(1024) __nv_bfloat16 g_feath[2][BN*GOUT], g_featl[2][BN*GOUT];
__device__ float g_cy[BB*NN], g_cx[BB*NN];
__device__ float g_tbh[BB], g_tbw[BB];
__device__ unsigned long long g_keys[8][NPAIR];
__device__ unsigned long long g_cand[8][NPAIR];
__device__ int g_ncand[8];
__device__ unsigned long long g_prefix[8];
__device__ int g_kneed[8];
__device__ unsigned int g_hist[8][256];
__device__ int g_ecount[8];
__device__ int   g_esrc[2][ETOT], g_edst[2][ETOT];
__device__ float g_ew[2][ETOT];
__device__ float g_deg[2][BN];
__device__ float g_xw[2][BN*GOUT];
__device__ float g_feat[2][BN*GOUT];

// ---------------- helpers ----------------
__device__ __forceinline__ uint32_t s2u(const void* p) {
    uint32_t a;
    asm("{ .reg .u64 t; cvta.to.shared.u64 t, %1; cvt.u32.u64 %0, t; }" : "=r"(a) : "l"(p));
    return a;
}
__device__ __forceinline__ void cp16(uint32_t dst, const void* src, int sz) {
    asm volatile("cp.async.cg.shared.global [%0], [%1], 16, %2;" :: "r"(dst), "l"(src), "r"(sz));
}
__device__ __forceinline__ void cp16f(uint32_t dst, const void* src) {
    asm volatile("cp.async.cg.shared.global [%0], [%1], 16;" :: "r"(dst), "l"(src));
}
__device__ __forceinline__ void cp_commit() { asm volatile("cp.async.commit_group;" ::: "memory"); }
__device__ __forceinline__ void cp_wait1() { asm volatile("cp.async.wait_group 1;" ::: "memory"); }
__device__ __forceinline__ void cp_wait0() { asm volatile("cp.async.wait_group 0;" ::: "memory"); }
__device__ __forceinline__ void split_bf16(float v, __nv_bfloat16& h, __nv_bfloat16& l) {
    h = __float2bfloat16(v);
    l = __float2bfloat16(v - __bfloat162float(h));
}

// emit one edge (shared by split + tie emit)
__device__ __forceinline__ void emit_edge(int seg, unsigned long long k) {
    int pos = atomicAdd(&g_ecount[seg], 1);
    if (pos < KEDGE) {
        int b = seg & 3, ty = seg >> 2;
        unsigned p = (unsigned)k & 0xFFFFFFFFu;
        int i = p / 511, r = p % 511;
        int j = r + (r >= i ? 1 : 0);
        float v = __uint_as_float(~(unsigned)(k >> 32));
        int slot = b*KEDGE + pos;
        int dst = b*NN + j;
        g_esrc[ty][slot] = b*NN + i;
        g_edst[ty][slot] = dst;
        g_ew[ty][slot] = v;
        atomicAdd(&g_deg[ty][dst], v);
    }
}

// ---------------- init ----------------
__global__ void k_init() {
    int t = blockIdx.x * blockDim.x + threadIdx.x;
    if (t < 8) { g_prefix[t] = 0ULL; g_kneed[t] = KEDGE; g_ecount[t] = 0; g_ncand[t] = 0; }
    if (t < 8*256) ((unsigned*)g_hist)[t] = 0u;
    if (t < 2*BN) {
        int ty = t / BN, i = t % BN;
        g_deg[ty][i] = 1.f;             // self loop weight
        g_esrc[ty][4*KEDGE + i] = i;
        g_edst[ty][4*KEDGE + i] = i;
        g_ew[ty][4*KEDGE + i] = 1.f;
    }
    if (t < 2*BN*GOUT) ((float*)g_feat)[t] = 0.f;
}

// ---------------- input NCHW fp32 -> NHWC split bf16 ----------------
__global__ void __launch_bounds__(256) k_cvt_in(const float* __restrict__ in) {
    __shared__ float sT[64][17];
    int ci0 = blockIdx.x * 64, x0 = blockIdx.y * 16;
    int by = blockIdx.z; int b = by / 48, y = by % 48;
    int t = threadIdx.x;
    int lx = t & 15, lc = t >> 4;
    const float* src = in + (size_t)b * CIN * 2304 + (size_t)y * 48 + x0;
#pragma unroll
    for (int j = 0; j < 4; j++)
        sT[lc + 16*j][lx] = src[(size_t)(ci0 + lc + 16*j) * 2304 + lx];
    __syncthreads();
    int wc = t & 63, wx = t >> 6;
#pragma unroll
    for (int j = 0; j < 4; j++) {
        float v = sT[wc][wx + 4*j];
        __nv_bfloat16 h, l; split_bf16(v, h, l);
        size_t o = ((size_t)(b*2304 + y*48 + x0 + wx + 4*j)) * 1024 + ci0 + wc;
        g_inh[o] = h; g_inl[o] = l;
    }
}

// ---------------- conv weights -> [tap][co][ci] split bf16 ----------------
__global__ void k_cvt_w(const float* __restrict__ W) {
    int co = blockIdx.x;
    for (int ci = threadIdx.x; ci < 1024; ci += 256) {
        const float* wp = W + ((size_t)co * 1024 + ci) * 9;
#pragma unroll
        for (int tap = 0; tap < 9; tap++) {
            __nv_bfloat16 h, l; split_bf16(wp[tap], h, l);
            size_t o = ((size_t)(tap*256 + co)) * 1024 + ci;
            g_wh[o] = h; g_wl[o] = l;
        }
    }
}

// ---------------- fused misc weight converts: y=0 W_cnn, y=1/2 W_grow/W_gcol, y=3 classifiers ----------------
__global__ void k_cvt_misc(const float* __restrict__ Wcnn,
                           const float* __restrict__ Wg0, const float* __restrict__ Wg1,
                           const float* __restrict__ Wr, const float* __restrict__ Wc) {
    int n = blockIdx.x, which = blockIdx.y;
    if (which == 0) {
        for (int kk = threadIdx.x; kk < 1024; kk += 256) {
            int p = kk >> 8, c = kk & 255;
            float v = Wcnn[(size_t)(c*4 + p) * 512 + n];
            __nv_bfloat16 h, l; split_bf16(v, h, l);
            g_wtch[(size_t)n*1024 + kk] = h;
            g_wtcl[(size_t)n*1024 + kk] = l;
        }
    } else if (which <= 2) {
        int ty = which - 1;
        const float* W = ty ? Wg1 : Wg0;
        for (int k = threadIdx.x; k < 768; k += 256) {
            __nv_bfloat16 h, l; split_bf16(W[(size_t)k * 512 + n], h, l);
            g_wtgh[ty][(size_t)n*768 + k] = h;
            g_wtgl[ty][(size_t)n*768 + k] = l;
        }
    } else {
        if (n < RCLS) {
            for (int k = threadIdx.x; k < 512; k += 256) {
                __nv_bfloat16 h, l; split_bf16(Wr[(size_t)k * RCLS + n], h, l);
                g_wtrh[(size_t)n*512 + k] = h;
                g_wtrl[(size_t)n*512 + k] = l;
            }
        } else if (n >= 256 && n < 256 + CCLS) {
            int nc = n - 256;
            for (int k = threadIdx.x; k < 512; k += 256) {
                __nv_bfloat16 h, l; split_bf16(Wc[(size_t)k * CCLS + nc], h, l);
                g_wtcch[(size_t)nc*512 + k] = h;
                g_wtccl[(size_t)nc*512 + k] = l;
            }
        }
    }
}

// ---------------- conv as 9 shifted GEMMs, HMMA split-bf16, 512 thr ----------------
// grid (2, 72): x = co-half (128 co), y = M-tile of 128 pixels.
__global__ void __launch_bounds__(512, 1) k_conv_wmma(const float* __restrict__ bias) {
    extern __shared__ char dsm_raw[];
    uint32_t raw = s2u(dsm_raw);
    uint32_t pad = (128u - (raw & 127u)) & 127u;
    char* sp = dsm_raw + pad;
    uint32_t spu = raw + pad;

    int t = threadIdx.x, wid = t >> 5;
    int co0 = blockIdx.x * 128;
    int tileM = blockIdx.y;
    int b = tileM / 18, loc0 = (tileM % 18) * 128;
    int wm = wid & 3, wn = wid >> 2;   // warp tile 32x32

    const __nv_bfloat16* inh_b = g_inh + (size_t)b * 2304 * 1024;
    const __nv_bfloat16* inl_b = g_inl + (size_t)b * 2304 * 1024;

    int rowL[2], qL[2], pyL[2], pxL[2];
#pragma unroll
    for (int i = 0; i < 2; i++) {
        int idx = t + 512*i;
        rowL[i] = idx >> 3; qL[i] = idx & 7;
        int l = loc0 + rowL[i];
        pyL[i] = l / 48; pxL[i] = l % 48;
    }

    wmma::fragment<wmma::accumulator, 16, 16, 16, float> acc[2][2];
#pragma unroll
    for (int i = 0; i < 2; i++)
#pragma unroll
        for (int j = 0; j < 2; j++) wmma::fill_fragment(acc[i][j], 0.f);

#define ISSUE_CHUNK(c) do {                                                       \
        int tap_ = (c) >> 4, ci0_ = ((c) & 15) << 6;                              \
        int dy_ = tap_ / 3 - 1, dx_ = tap_ % 3 - 1;                               \
        uint32_t sb_ = spu + ((c) & 1) * CSTG;                                    \
        _Pragma("unroll")                                                         \
        for (int i = 0; i < 2; i++) {                                             \
            int row_ = rowL[i], q_ = qL[i];                                       \
            uint32_t so_ = (uint32_t)(row_*(CLD*2) + q_*16);                      \
            int ys_ = pyL[i] + dy_, xs_ = pxL[i] + dx_;                           \
            bool ok_ = ((unsigned)ys_ < 48u) & ((unsigned)xs_ < 48u);             \
            size_t go_ = ok_ ? ((size_t)(ys_*48 + xs_)*1024 + ci0_ + q_*8) : 0;   \
            int sz_ = ok_ ? 16 : 0;                                               \
            cp16(sb_ + so_,          inh_b + go_, sz_);                           \
            cp16(sb_ + CMAT + so_,   inl_b + go_, sz_);                           \
            size_t wo_ = (size_t)(tap_*256 + co0 + row_)*1024 + ci0_ + q_*8;      \
            cp16f(sb_ + 2*CMAT + so_, g_wh + wo_);                                \
            cp16f(sb_ + 3*CMAT + so_, g_wl + wo_);                                \
        }                                                                         \
    } while (0)

    ISSUE_CHUNK(0);
    cp_commit();

    for (int c = 0; c < 144; c++) {
        if (c + 1 < 144) { ISSUE_CHUNK(c + 1); cp_commit(); cp_wait1(); }
        else             { cp_wait0(); }
        __syncthreads();
        const char* sb = sp + (c & 1) * CSTG;
        const __nv_bfloat16* Ah = (const __nv_bfloat16*)(sb);
        const __nv_bfloat16* Al = (const __nv_bfloat16*)(sb + CMAT);
        const __nv_bfloat16* Bh = (const __nv_bfloat16*)(sb + 2*CMAT);
        const __nv_bfloat16* Bl = (const __nv_bfloat16*)(sb + 3*CMAT);
#pragma unroll
        for (int kk = 0; kk < 64; kk += 16) {
            wmma::fragment<wmma::matrix_a, 16, 16, 16, __nv_bfloat16, wmma::row_major> ah[2], al[2];
            wmma::fragment<wmma::matrix_b, 16, 16, 16, __nv_bfloat16, wmma::col_major> bh[2], bl[2];
#pragma unroll
            for (int i = 0; i < 2; i++) {
                wmma::load_matrix_sync(ah[i], Ah + (wm*32 + i*16)*CLD + kk, CLD);
                wmma::load_matrix_sync(al[i], Al + (wm*32 + i*16)*CLD + kk, CLD);
            }
#pragma unroll
            for (int j = 0; j < 2; j++) {
                wmma::load_matrix_sync(bh[j], Bh + (wn*32 + j*16)*CLD + kk, CLD);
                wmma::load_matrix_sync(bl[j], Bl + (wn*32 + j*16)*CLD + kk, CLD);
            }
#pragma unroll
            for (int i = 0; i < 2; i++)
#pragma unroll
                for (int j = 0; j < 2; j++) {
                    wmma::mma_sync(acc[i][j], ah[i], bh[j], acc[i][j]);
                    wmma::mma_sync(acc[i][j], al[i], bh[j], acc[i][j]);
                    wmma::mma_sync(acc[i][j], ah[i], bl[j], acc[i][j]);
                }
        }
        __syncthreads();
    }
#undef ISSUE_CHUNK

    float* sE = (float*)sp;
#pragma unroll
    for (int i = 0; i < 2; i++)
#pragma unroll
        for (int j = 0; j < 2; j++)
            wmma::store_matrix_sync(sE + (wm*32 + i*16)*128 + wn*32 + j*16,
                                    acc[i][j], 128, wmma::mem_row_major);
    __syncthreads();
#pragma unroll
    for (int r = 0; r < 8; r++) {
        int idx = t + 512*r;
        int row = idx >> 5, col = (idx & 31) * 4;
        float4 v = *(const float4*)&sE[row*128 + col];
        v.x = fmaxf(v.x + bias[co0+col+0], 0.f);
        v.y = fmaxf(v.y + bias[co0+col+1], 0.f);
        v.z = fmaxf(v.z + bias[co0+col+2], 0.f);
        v.w = fmaxf(v.w + bias[co0+col+3], 0.f);
        int pix = b*2304 + loc0 + row;
        *(float4*)&g_dec[(size_t)pix*256 + co0 + col] = v;
    }
}

// ---------------- split-bf16 HMMA GEMM: C[M,N] = A[M,K] * B[N,K]^T ----------------
// EPI 0: fp32 -> C. EPI 1: relu(+bias) -> split bf16 Ch/Cl. EPI 2: leaky(+bias) -> C (runtime N=Nn, guarded).
template<int EPI>
__global__ void __launch_bounds__(512, 1) k_hgemm(const __nv_bfloat16* __restrict__ Agh,
                                                  const __nv_bfloat16* __restrict__ Agl,
                                                  const __nv_bfloat16* __restrict__ Bgh,
                                                  const __nv_bfloat16* __restrict__ Bgl,
                                                  float* C, __nv_bfloat16* Ch, __nv_bfloat16* Cl,
                                                  const float* __restrict__ bias,
                                                  int K, int ldc, int colofs, int Nn) {
    extern __shared__ char dsm_raw[];
    uint32_t raw = s2u(dsm_raw);
    uint32_t pad = (128u - (raw & 127u)) & 127u;
    char* sp = dsm_raw + pad;
    uint32_t spu = raw + pad;

    int t = threadIdx.x, wid = t >> 5;
    int n0 = blockIdx.x * 128, m0 = blockIdx.y * 128;
    int wm = wid & 3, wn = wid >> 2;

    int rowL[2], qL[2];
#pragma unroll
    for (int i = 0; i < 2; i++) {
        int idx = t + 512*i;
        rowL[i] = idx >> 3; qL[i] = idx & 7;
    }

    wmma::fragment<wmma::accumulator, 16, 16, 16, float> acc[2][2];
#pragma unroll
    for (int i = 0; i < 2; i++)
#pragma unroll
        for (int j = 0; j < 2; j++) wmma::fill_fragment(acc[i][j], 0.f);

    int nch = K >> 6;
#define ISSUE_G(c) do {                                                          \
        int k0_ = (c) << 6;                                                      \
        uint32_t sb_ = spu + ((c) & 1) * CSTG;                                   \
        _Pragma("unroll")                                                        \
        for (int i = 0; i < 2; i++) {                                            \
            int row_ = rowL[i], q_ = qL[i];                                      \
            uint32_t so_ = (uint32_t)(row_*(CLD*2) + q_*16);                     \
            size_t ao_ = (size_t)(m0 + row_)*K + k0_ + q_*8;                     \
            cp16f(sb_ + so_,        Agh + ao_);                                  \
            cp16f(sb_ + CMAT + so_, Agl + ao_);                                  \
            int bn_ = n0 + row_; if (bn_ >= Nn) bn_ = Nn - 1;                    \
            size_t bo_ = (size_t)bn_*K + k0_ + q_*8;                             \
            cp16f(sb_ + 2*CMAT + so_, Bgh + bo_);                                \
            cp16f(sb_ + 3*CMAT + so_, Bgl + bo_);                                \
        }                                                                        \
    } while (0)

    ISSUE_G(0);
    cp_commit();
    for (int c = 0; c < nch; c++) {
        if (c + 1 < nch) { ISSUE_G(c + 1); cp_commit(); cp_wait1(); }
        else             { cp_wait0(); }
        __syncthreads();
        const char* sb = sp + (c & 1) * CSTG;
        const __nv_bfloat16* Ah = (const __nv_bfloat16*)(sb);
        const __nv_bfloat16* Al = (const __nv_bfloat16*)(sb + CMAT);
        const __nv_bfloat16* Bh = (const __nv_bfloat16*)(sb + 2*CMAT);
        const __nv_bfloat16* Bl = (const __nv_bfloat16*)(sb + 3*CMAT);
#pragma unroll
        for (int kk = 0; kk < 64; kk += 16) {
            wmma::fragment<wmma::matrix_a, 16, 16, 16, __nv_bfloat16, wmma::row_major> ah[2], al[2];
            wmma::fragment<wmma::matrix_b, 16, 16, 16, __nv_bfloat16, wmma::col_major> bh[2], bl[2];
#pragma unroll
            for (int i = 0; i < 2; i++) {
                wmma::load_matrix_sync(ah[i], Ah + (wm*32 + i*16)*CLD + kk, CLD);
                wmma::load_matrix_sync(al[i], Al + (wm*32 + i*16)*CLD + kk, CLD);
            }
#pragma unroll
            for (int j = 0; j < 2; j++) {
                wmma::load_matrix_sync(bh[j], Bh + (wn*32 + j*16)*CLD + kk, CLD);
                wmma::load_matrix_sync(bl[j], Bl + (wn*32 + j*16)*CLD + kk, CLD);
            }
#pragma unroll
            for (int i = 0; i < 2; i++)
#pragma unroll
                for (int j = 0; j < 2; j++) {
                    wmma::mma_sync(acc[i][j], ah[i], bh[j], acc[i][j]);
                    wmma::mma_sync(acc[i][j], al[i], bh[j], acc[i][j]);
                    wmma::mma_sync(acc[i][j], ah[i], bl[j], acc[i][j]);
                }
        }
        __syncthreads();
    }
#undef ISSUE_G

    float* sE = (float*)sp;
#pragma unroll
    for (int i = 0; i < 2; i++)
#pragma unroll
        for (int j = 0; j < 2; j++)
            wmma::store_matrix_sync(sE + (wm*32 + i*16)*128 + wn*32 + j*16,
                                    acc[i][j], 128, wmma::mem_row_major);
    __syncthreads();
#pragma unroll
    for (int r = 0; r < 8; r++) {
        int idx = t + 512*r;
        int row = idx >> 5, col = (idx & 31) * 4;
        float4 v = *(const float4*)&sE[row*128 + col];
        if (EPI == 0) {
            *(float4*)&C[(size_t)(m0 + row)*ldc + n0 + col] = v;
        } else if (EPI == 1) {
            v.x = fmaxf(v.x + bias[n0+col+0], 0.f);
            v.y = fmaxf(v.y + bias[n0+col+1], 0.f);
            v.z = fmaxf(v.z + bias[n0+col+2], 0.f);
            v.w = fmaxf(v.w + bias[n0+col+3], 0.f);
            __nv_bfloat16 h0,l0,h1,l1,h2,l2,h3,l3;
            split_bf16(v.x,h0,l0); split_bf16(v.y,h1,l1);
            split_bf16(v.z,h2,l2); split_bf16(v.w,h3,l3);
            size_t o = (size_t)(m0 + row)*ldc + colofs + n0 + col;
            __nv_bfloat162* ph = (__nv_bfloat162*)&Ch[o];
            __nv_bfloat162* pl = (__nv_bfloat162*)&Cl[o];
            ph[0] = __nv_bfloat162(h0, h1); ph[1] = __nv_bfloat162(h2, h3);
            pl[0] = __nv_bfloat162(l0, l1); pl[1] = __nv_bfloat162(l2, l3);
        } else {
            float vv[4] = {v.x, v.y, v.z, v.w};
#pragma unroll
            for (int e = 0; e < 4; e++) {
                int n = n0 + col + e;
                if (n < Nn) {
                    float u = vv[e] + bias[n];
                    u = (u >= 0.f) ? u : 0.01f * u;
                    C[(size_t)(m0 + row)*ldc + n] = u;
                }
            }
        }
    }
}

// ---------------- box feature MLP -> fusion split bf16 ----------------
__global__ void k_boxfeat(const float* __restrict__ boxes,
                          const float* __restrict__ Wb, const float* __restrict__ bb) {
    int n = blockIdx.x, co = threadIdx.x;
    float f0 = boxes[n*4+0], f1 = boxes[n*4+1], f2 = boxes[n*4+2], f3 = boxes[n*4+3];
    float cx = (f0 + f2) / 2.0f, cy = (f1 + f3) / 2.0f;
    float b0 = cx / 48.0f, b1 = cy / 48.0f;
    float b2 = (f2 - f0) / 48.0f, b3 = (f3 - f1) / 48.0f;
    float v = bb[co] + b0*Wb[co] + b1*Wb[256+co] + b2*Wb[512+co] + b3*Wb[768+co];
    v = fmaxf(v, 0.f);
    __nv_bfloat16 h, l; split_bf16(v, h, l);
    g_fush[(size_t)n*FUS + co] = h;
    g_fusl[(size_t)n*FUS + co] = l;
}

// ---------------- cx/cy + table extents ----------------
__global__ void k_cxcy(const float* __restrict__ boxes, const float* __restrict__ scales,
                       const float* __restrict__ pdls, const float* __restrict__ pdts) {
    int b = blockIdx.x, i = threadIdx.x;
    float sc = scales[b], pl = pdls[b], pt = pdts[b];
    const float* bx = boxes + ((size_t)b*NN + i)*4;
    float o0 = (bx[0]-pl)/sc, o1 = (bx[1]-pt)/sc, o2 = (bx[2]-pl)/sc, o3 = (bx[3]-pt)/sc;
    g_cx[b*NN+i] = (o0 + o2) * 0.5f;
    g_cy[b*NN+i] = (o1 + o3) * 0.5f;
    __shared__ float sw[512], sh[512];
    sw[i] = fmaxf(o0, o2); sh[i] = fmaxf(o1, o3);
    __syncthreads();
    for (int s = 256; s > 0; s >>= 1) {
        if (i < s) { sw[i] = fmaxf(sw[i], sw[i+s]); sh[i] = fmaxf(sh[i], sh[i+s]); }
        __syncthreads();
    }
    if (i == 0) { g_tbw[b] = sw[0]; g_tbh[b] = sh[0]; }
}

// ---------------- pair attr keys + fused pass-1 hist (smem-privatized) ----------------
__global__ void k_keys() {
    __shared__ unsigned shr[256], shc[256];
    int t = threadIdx.x;
    if (t < 256) { shr[t] = 0u; shc[t] = 0u; }
    __syncthreads();
    int p = blockIdx.x*256 + t;
    int b = blockIdx.y;
    if (p < NPAIR) {
        int i = p / 511, r = p % 511;
        int j = r + (r >= i ? 1 : 0);
        float cys = g_cy[b*NN+i], cyd = g_cy[b*NN+j];
        float cxs = g_cx[b*NN+i], cxd = g_cx[b*NN+j];
        float dr = (cys - cyd) * 5.0f / g_tbh[b];
        float dc = (cxs - cxd) * 5.0f / g_tbw[b];
        float vr = expf(-(dr*dr));
        float vc = expf(-(dc*dc));
        unsigned long long kr = (((unsigned long long)(~__float_as_uint(vr))) << 32) | (unsigned)p;
        unsigned long long kc = (((unsigned long long)(~__float_as_uint(vc))) << 32) | (unsigned)p;
        g_keys[b][p]     = kr;
        g_keys[4 + b][p] = kc;
        atomicAdd(&shr[(unsigned)(kr >> 56)], 1u);
        atomicAdd(&shc[(unsigned)(kc >> 56)], 1u);
    }
    __syncthreads();
    if (t < 256) {
        if (shr[t]) atomicAdd(&g_hist[b][t], shr[t]);
        if (shc[t]) atomicAdd(&g_hist[4 + b][t], shc[t]);
    }
}

// ---------------- radix select: full-array hist (value bytes) ----------------
__global__ void k_hist(int shift) {
    __shared__ unsigned sh[256];
    int seg = blockIdx.y;
    if (threadIdx.x < 256) sh[threadIdx.x] = 0u;
    __syncthreads();
    unsigned long long pref = g_prefix[seg];
    for (int idx = blockIdx.x*blockDim.x + threadIdx.x; idx < NPAIR; idx += gridDim.x*blockDim.x) {
        unsigned long long k = g_keys[seg][idx];
        if ((((k ^ pref) >> shift) >> 8) == 0ULL)
            atomicAdd(&sh[(unsigned)(k >> shift) & 255u], 1u);
    }
    __syncthreads();
    if (threadIdx.x < 256 && sh[threadIdx.x])
        atomicAdd(&g_hist[seg][threadIdx.x], sh[threadIdx.x]);
}

// ---------------- tie-buffer hist (index bytes) ----------------
__global__ void k_histc(int shift) {
    __shared__ unsigned sh[256];
    int seg = blockIdx.y;
    if (threadIdx.x < 256) sh[threadIdx.x] = 0u;
    __syncthreads();
    unsigned long long pref = g_prefix[seg];
    int n = g_ncand[seg];
    for (int idx = blockIdx.x*blockDim.x + threadIdx.x; idx < n; idx += gridDim.x*blockDim.x) {
        unsigned long long k = g_cand[seg][idx];
        if ((((k ^ pref) >> shift) >> 8) == 0ULL)
            atomicAdd(&sh[(unsigned)(k >> shift) & 255u], 1u);
    }
    __syncthreads();
    if (threadIdx.x < 256 && sh[threadIdx.x])
        atomicAdd(&g_hist[seg][threadIdx.x], sh[threadIdx.x]);
}

__global__ void k_scan(int shift) {
    int seg = threadIdx.x;
    if (seg >= 8) return;
    int need = g_kneed[seg];
    unsigned long long pref = g_prefix[seg];
    int cum = 0, chosen = 255, newneed = need;
    bool done = false;
    for (int bin = 0; bin < 256; bin++) {
        int c = (int)g_hist[seg][bin];
        g_hist[seg][bin] = 0u;
        if (!done && cum + c >= need) { chosen = bin; newneed = need - cum; done = true; }
        cum += c;
    }
    g_prefix[seg] = pref | ((unsigned long long)chosen << shift);
    g_kneed[seg] = newneed;
}

// ---------------- split: emit value_top32 < boundary, collect exact-value ties ----------------
__global__ void k_split() {
    int seg = blockIdx.y;
    unsigned bound = (unsigned)(g_prefix[seg] >> 32);
    for (int idx = blockIdx.x*blockDim.x + threadIdx.x; idx < NPAIR; idx += gridDim.x*blockDim.x) {
        unsigned long long k = g_keys[seg][idx];
        unsigned top = (unsigned)(k >> 32);
        if (top < bound) {
            emit_edge(seg, k);
        } else if (top == bound) {
            int pos = atomicAdd(&g_ncand[seg], 1);
            g_cand[seg][pos] = k;
        }
    }
}

// ---------------- final emit over ties ----------------
__global__ void k_emitc() {
    int seg = blockIdx.y;
    unsigned long long pref = g_prefix[seg];
    int n = g_ncand[seg];
    for (int idx = blockIdx.x*blockDim.x + threadIdx.x; idx < n; idx += gridDim.x*blockDim.x) {
        unsigned long long k = g_cand[seg][idx];
        if (k <= pref) emit_edge(seg, k);
    }
}

// ---------------- ROI align 2x2 -> split bf16 ----------------
__global__ void k_roi(const float* __restrict__ boxes) {
    int n = blockIdx.x, c = threadIdx.x;
    int b = n >> 9;
    float x1 = boxes[n*4+0], y1 = boxes[n*4+1], x2 = boxes[n*4+2], y2 = boxes[n*4+3];
    float bw = (x2 - x1) / 2.0f, bh = (y2 - y1) / 2.0f;
    const float* base = g_dec + (size_t)b * HH * WWW * CO;
#pragma unroll
    for (int p = 0; p < 4; p++) {
        float py = y1 + (0.5f + (float)(p >> 1)) * bh;
        float px = x1 + (0.5f + (float)(p & 1)) * bw;
        py = fminf(fmaxf(py, 0.f), 47.f);
        px = fminf(fmaxf(px, 0.f), 47.f);
        int y0 = (int)floorf(py), x0 = (int)floorf(px);
        int y1i = min(y0 + 1, 47), x1i = min(x0 + 1, 47);
        float wy = py - (float)y0, wx = px - (float)x0;
        float f00 = base[(y0*48 + x0 )*CO + c];
        float f01 = base[(y0*48 + x1i)*CO + c];
        float f10 = base[(y1i*48 + x0 )*CO + c];
        float f11 = base[(y1i*48 + x1i)*CO + c];
        float v = f00*(1.f-wy)*(1.f-wx) + f01*(1.f-wy)*wx + f10*wy*(1.f-wx) + f11*wy*wx;
        __nv_bfloat16 h, l; split_bf16(v, h, l);
        g_cnnh[(size_t)n*1024 + p*256 + c] = h;
        g_cnnl[(size_t)n*1024 + p*256 + c] = l;
    }
}

// ---------------- GCN aggregation scatter (4 edges per block) ----------------
__global__ void __launch_bounds__(512) k_agg() {
    int g = threadIdx.x >> 7, j0 = threadIdx.x & 127;
    int e = blockIdx.x * 4 + g, ty = blockIdx.y;
    if (e >= ETOT) return;
    int src = g_esrc[ty][e], dst = g_edst[ty][e];
    float norm = rsqrtf(g_deg[ty][src]) * g_ew[ty][e] * rsqrtf(g_deg[ty][dst]);
    const float* xs = g_xw[ty] + (size_t)src * GOUT;
    float* fd = g_feat[ty] + (size_t)dst * GOUT;
#pragma unroll
    for (int j = j0; j < GOUT; j += 128)
        atomicAdd(&fd[j], norm * xs[j]);
}

// ---------------- bias+relu -> split bf16 features ----------------
__global__ void k_final(const float* __restrict__ bg0, const float* __restrict__ bg1) {
    int i = blockIdx.x*blockDim.x + threadIdx.x;
    if (i < 2*BN*GOUT) {
        int ty = i / (BN*GOUT);
        int r = i % (BN*GOUT);
        int j = r % GOUT;
        float bv = ty ? bg1[j] : bg0[j];
        float v = fmaxf(((float*)g_feat)[i] + bv, 0.f);
        __nv_bfloat16 h, l; split_bf16(v, h, l);
        ((__nv_bfloat16*)g_feath)[i] = h;
        ((__nv_bfloat16*)g_featl)[i] = l;
    }
}

// ---------------- launch ----------------
extern "C" void kernel_launch(void* const* d_in, const int* in_sizes, int n_in,
                              void* d_out, int out_size) {
    const float* input  = (const float*)d_in[0];
    const float* boxes  = (const float*)d_in[1];
    const float* scales = (const float*)d_in[2];
    const float* pdls   = (const float*)d_in[3];
    const float* pdts   = (const float*)d_in[4];
    const float* W_dec  = (const float*)d_in[5];
    const float* b_dec  = (const float*)d_in[6];
    const float* W_box  = (const float*)d_in[7];
    const float* b_box  = (const float*)d_in[8];
    const float* W_cnn  = (const float*)d_in[9];
    const float* b_cnn  = (const float*)d_in[10];
    const float* W_grow = (const float*)d_in[11];
    const float* b_grow = (const float*)d_in[12];
    const float* W_gcol = (const float*)d_in[13];
    const float* b_gcol = (const float*)d_in[14];
    const float* W_rcls = (const float*)d_in[15];
    const float* b_rcls = (const float*)d_in[16];
    const float* W_ccls = (const float*)d_in[17];
    const float* b_ccls = (const float*)d_in[18];
    float* out = (float*)d_out;

    void *p1, *p2, *p3, *p4, *p5, *p6, *p7, *p8, *p9, *pb, *pc, *pd, *pe, *pf, *pg;
    cudaGetSymbolAddress(&p1, g_cnnh);  cudaGetSymbolAddress(&p2, g_cnnl);
    cudaGetSymbolAddress(&p3, g_fush);  cudaGetSymbolAddress(&p4, g_fusl);
    cudaGetSymbolAddress(&p5, g_wtch);  cudaGetSymbolAddress(&p6, g_wtcl);
    cudaGetSymbolAddress(&p7, g_wtgh);  cudaGetSymbolAddress(&p8, g_wtgl);
    cudaGetSymbolAddress(&p9, g_xw);
    cudaGetSymbolAddress(&pb, g_feath); cudaGetSymbolAddress(&pc, g_featl);
    cudaGetSymbolAddress(&pd, g_wtrh);  cudaGetSymbolAddress(&pe, g_wtrl);
    cudaGetSymbolAddress(&pf, g_wtcch); cudaGetSymbolAddress(&pg, g_wtccl);
    __nv_bfloat16* cnnh = (__nv_bfloat16*)p1;
    __nv_bfloat16* cnnl = (__nv_bfloat16*)p2;
    __nv_bfloat16* fush = (__nv_bfloat16*)p3;
    __nv_bfloat16* fusl = (__nv_bfloat16*)p4;
    __nv_bfloat16* wtch = (__nv_bfloat16*)p5;
    __nv_bfloat16* wtcl = (__nv_bfloat16*)p6;
    __nv_bfloat16* wtgh = (__nv_bfloat16*)p7;
    __nv_bfloat16* wtgl = (__nv_bfloat16*)p8;
    float* xw0 = (float*)p9;
    float* xw1 = xw0 + (size_t)BN*GOUT;
    __nv_bfloat16* feath = (__nv_bfloat16*)pb;
    __nv_bfloat16* featl = (__nv_bfloat16*)pc;
    __nv_bfloat16* wtrh = (__nv_bfloat16*)pd;
    __nv_bfloat16* wtrl = (__nv_bfloat16*)pe;
    __nv_bfloat16* wtcch = (__nv_bfloat16*)pf;
    __nv_bfloat16* wtccl = (__nv_bfloat16*)pg;

    cudaFuncSetAttribute(k_conv_wmma, cudaFuncAttributeMaxDynamicSharedMemorySize, CSMEM);
    cudaFuncSetAttribute(k_hgemm<0>, cudaFuncAttributeMaxDynamicSharedMemorySize, CSMEM);
    cudaFuncSetAttribute(k_hgemm<1>, cudaFuncAttributeMaxDynamicSharedMemorySize, CSMEM);
    cudaFuncSetAttribute(k_hgemm<2>, cudaFuncAttributeMaxDynamicSharedMemorySize, CSMEM);

    k_init<<<8192, 256>>>();
    k_cvt_in<<<dim3(16, 3, BB*48), 256>>>(input);
    k_cvt_w<<<CO, 256>>>(W_dec);
    k_cvt_misc<<<dim3(512, 4), 256>>>(W_cnn, W_grow, W_gcol, W_rcls, W_ccls);
    k_conv_wmma<<<dim3(2, 72), 512, CSMEM>>>(b_dec);
    k_boxfeat<<<BN, 256>>>(boxes, W_box, b_box);
    k_cxcy<<<BB, 512>>>(boxes, scales, pdls, pdts);
    // --- top-k select ---
    k_keys<<<dim3(1022, 4), 256>>>();
    k_scan<<<1, 8>>>(56);
    k_hist<<<dim3(64, 8), 256>>>(48);  k_scan<<<1, 8>>>(48);
    k_hist<<<dim3(64, 8), 256>>>(40);  k_scan<<<1, 8>>>(40);
    k_hist<<<dim3(64, 8), 256>>>(32);  k_scan<<<1, 8>>>(32);
    k_split<<<dim3(64, 8), 256>>>();
    k_histc<<<dim3(8, 8), 256>>>(16);  k_scan<<<1, 8>>>(16);
    k_histc<<<dim3(8, 8), 256>>>(8);   k_scan<<<1, 8>>>(8);
    k_histc<<<dim3(8, 8), 256>>>(0);   k_scan<<<1, 8>>>(0);
    k_emitc<<<dim3(8, 8), 256>>>();
    k_roi<<<BN, 256>>>(boxes);
    k_hgemm<1><<<dim3(4, 16), 512, CSMEM>>>(cnnh, cnnl, wtch, wtcl,
                                            nullptr, fush, fusl, b_cnn, 1024, FUS, 256, 512);
    k_hgemm<0><<<dim3(4, 16), 512, CSMEM>>>(fush, fusl, wtgh, wtgl,
                                            xw0, nullptr, nullptr, nullptr, 768, 512, 0, 512);
    k_hgemm<0><<<dim3(4, 16), 512, CSMEM>>>(fush, fusl, wtgh + (size_t)512*768, wtgl + (size_t)512*768,
                                            xw1, nullptr, nullptr, nullptr, 768, 512, 0, 512);
    k_agg<<<dim3((ETOT + 3)/4, 2), 512>>>();
    k_final<<<(2*BN*GOUT + 255)/256, 256>>>(b_grow, b_gcol);
    // classifiers on HMMA (leaky relu, runtime N)
    k_hgemm<2><<<dim3(2, 16), 512, CSMEM>>>(feath, featl, wtrh, wtrl,
                                            out, nullptr, nullptr, b_rcls, 512, RCLS, 0, RCLS);
    k_hgemm<2><<<dim3(1, 16), 512, CSMEM>>>(feath + (size_t)BN*GOUT, featl + (size_t)BN*GOUT,
                                            wtcch, wtccl,
                                            out + (size_t)BN*RCLS, nullptr, nullptr, b_ccls, 512, CCLS, 0, CCLS);
}

// round 16
// speedup vs baseline: 1.1037x; 1.0008x over previous
#include <cuda_runtime.h>
#include <cuda_bf16.h>
#include <mma.h>
#include <cstdint>
#include <math.h>

using namespace nvcuda;

#define BB 4
#define NN 512
#define BN 2048
#define CIN 1024
#define HH 48
#define WWW 48
#define CO 256
#define NPAIR 261632          // 512*511
#define KEDGE 4096
#define ETOT (4*KEDGE + BN)   // 18432 edges per graph type (incl self loops)
#define GOUT 512
#define FUS 768
#define RCLS 228
#define CCLS 116

// HMMA tile kernels: 128x128 CTA tile, K-chunk 64, 512 threads.
#define CLD   72
#define CMAT  18432
#define CSTG  73728            // 4 mats (Ah|Al|Bh|Bl)
#define CSMEM (2*CSTG + 256)   // 147712

// ---------------- device scratch ----------------
__device__ __align__(1024) float g_dec[BB*HH*WWW*CO];
__device__ __align__(1024) __nv_bfloat16 g_inh[BB*HH*WWW*CIN];
__device__ __align__(1024) __nv_bfloat16 g_inl[BB*HH*WWW*CIN];
__device__ __align__(1024) __nv_bfloat16 g_wh[9*CO*CIN];
__device__ __align__(1024) __nv_bfloat16 g_wl[9*CO*CIN];
__device__ __align__(1024) __nv_bfloat16 g_cnnh[BN*1024], g_cnnl[BN*1024];
__device__ __align__(1024) __nv_bfloat16 g_fush[BN*FUS], g_fusl[BN*FUS];
__device__ __align__(1024) __nv_bfloat16 g_wtch[512*1024], g_wtcl[512*1024];
__device__ __align__(1024) __nv_bfloat16 g_wtgh[2][512*768], g_wtgl[2][512*768];
__device__ __align__(1024) __nv_bfloat16 g_wtrh[RCLS*512], g_wtrl[RCLS*512];
__device__ __align__(1024) __nv_bfloat16 g_wtcch[CCLS*512], g_wtccl[CCLS*512];
__device__ __align__(1024) __nv_bfloat16 g_feath[2][BN*GOUT], g_featl[2][BN*GOUT];
__device__ float g_cy[BB*NN], g_cx[BB*NN];
__device__ float g_tbh[BB], g_tbw[BB];
__device__ unsigned long long g_keys[8][NPAIR];
__device__ unsigned long long g_cand[8][NPAIR];
__device__ int g_ncand[8];
__device__ unsigned long long g_prefix[8];
__device__ int g_kneed[8];
__device__ unsigned int g_hist[8][256];
__device__ int g_ecount[8];
__device__ int   g_esrc[2][ETOT], g_edst[2][ETOT];
__device__ float g_ew[2][ETOT];
__device__ float g_deg[2][BN];
__device__ float g_xw[2][BN*GOUT];
__device__ float g_feat[2][BN*GOUT];

// ---------------- helpers ----------------
__device__ __forceinline__ uint32_t s2u(const void* p) {
    uint32_t a;
    asm("{ .reg .u64 t; cvta.to.shared.u64 t, %1; cvt.u32.u64 %0, t; }" : "=r"(a) : "l"(p));
    return a;
}
__device__ __forceinline__ void cp16(uint32_t dst, const void* src, int sz) {
    asm volatile("cp.async.cg.shared.global [%0], [%1], 16, %2;" :: "r"(dst), "l"(src), "r"(sz));
}
__device__ __forceinline__ void cp16f(uint32_t dst, const void* src) {
    asm volatile("cp.async.cg.shared.global [%0], [%1], 16;" :: "r"(dst), "l"(src));
}
__device__ __forceinline__ void cp_commit() { asm volatile("cp.async.commit_group;" ::: "memory"); }
__device__ __forceinline__ void cp_wait1() { asm volatile("cp.async.wait_group 1;" ::: "memory"); }
__device__ __forceinline__ void cp_wait0() { asm volatile("cp.async.wait_group 0;" ::: "memory"); }
__device__ __forceinline__ void split_bf16(float v, __nv_bfloat16& h, __nv_bfloat16& l) {
    h = __float2bfloat16(v);
    l = __float2bfloat16(v - __bfloat162float(h));
}

// emit one edge (shared by split + tie emit)
__device__ __forceinline__ void emit_edge(int seg, unsigned long long k) {
    int pos = atomicAdd(&g_ecount[seg], 1);
    if (pos < KEDGE) {
        int b = seg & 3, ty = seg >> 2;
        unsigned p = (unsigned)k & 0xFFFFFFFFu;
        int i = p / 511, r = p % 511;
        int j = r + (r >= i ? 1 : 0);
        float v = __uint_as_float(~(unsigned)(k >> 32));
        int slot = b*KEDGE + pos;
        int dst = b*NN + j;
        g_esrc[ty][slot] = b*NN + i;
        g_edst[ty][slot] = dst;
        g_ew[ty][slot] = v;
        atomicAdd(&g_deg[ty][dst], v);
    }
}

// ---------------- init ----------------
__global__ void k_init() {
    int t = blockIdx.x * blockDim.x + threadIdx.x;
    if (t < 8) { g_prefix[t] = 0ULL; g_kneed[t] = KEDGE; g_ecount[t] = 0; g_ncand[t] = 0; }
    if (t < 8*256) ((unsigned*)g_hist)[t] = 0u;
    if (t < 2*BN) {
        int ty = t / BN, i = t % BN;
        g_deg[ty][i] = 1.f;             // self loop weight
        g_esrc[ty][4*KEDGE + i] = i;
        g_edst[ty][4*KEDGE + i] = i;
        g_ew[ty][4*KEDGE + i] = 1.f;
    }
    if (t < 2*BN*GOUT) ((float*)g_feat)[t] = 0.f;
}

// ---------------- input NCHW fp32 -> NHWC split bf16 ----------------
__global__ void __launch_bounds__(256) k_cvt_in(const float* __restrict__ in) {
    __shared__ float sT[64][17];
    int ci0 = blockIdx.x * 64, x0 = blockIdx.y * 16;
    int by = blockIdx.z; int b = by / 48, y = by % 48;
    int t = threadIdx.x;
    int lx = t & 15, lc = t >> 4;
    const float* src = in + (size_t)b * CIN * 2304 + (size_t)y * 48 + x0;
#pragma unroll
    for (int j = 0; j < 4; j++)
        sT[lc + 16*j][lx] = src[(size_t)(ci0 + lc + 16*j) * 2304 + lx];
    __syncthreads();
    int wc = t & 63, wx = t >> 6;
#pragma unroll
    for (int j = 0; j < 4; j++) {
        float v = sT[wc][wx + 4*j];
        __nv_bfloat16 h, l; split_bf16(v, h, l);
        size_t o = ((size_t)(b*2304 + y*48 + x0 + wx + 4*j)) * 1024 + ci0 + wc;
        g_inh[o] = h; g_inl[o] = l;
    }
}

// ---------------- conv weights -> [tap][co][ci] split bf16 ----------------
__global__ void k_cvt_w(const float* __restrict__ W) {
    int co = blockIdx.x;
    for (int ci = threadIdx.x; ci < 1024; ci += 256) {
        const float* wp = W + ((size_t)co * 1024 + ci) * 9;
#pragma unroll
        for (int tap = 0; tap < 9; tap++) {
            __nv_bfloat16 h, l; split_bf16(wp[tap], h, l);
            size_t o = ((size_t)(tap*256 + co)) * 1024 + ci;
            g_wh[o] = h; g_wl[o] = l;
        }
    }
}

// ---------------- fused misc weight converts: y=0 W_cnn, y=1/2 W_grow/W_gcol, y=3 classifiers ----------------
__global__ void k_cvt_misc(const float* __restrict__ Wcnn,
                           const float* __restrict__ Wg0, const float* __restrict__ Wg1,
                           const float* __restrict__ Wr, const float* __restrict__ Wc) {
    int n = blockIdx.x, which = blockIdx.y;
    if (which == 0) {
        for (int kk = threadIdx.x; kk < 1024; kk += 256) {
            int p = kk >> 8, c = kk & 255;
            float v = Wcnn[(size_t)(c*4 + p) * 512 + n];
            __nv_bfloat16 h, l; split_bf16(v, h, l);
            g_wtch[(size_t)n*1024 + kk] = h;
            g_wtcl[(size_t)n*1024 + kk] = l;
        }
    } else if (which <= 2) {
        int ty = which - 1;
        const float* W = ty ? Wg1 : Wg0;
        for (int k = threadIdx.x; k < 768; k += 256) {
            __nv_bfloat16 h, l; split_bf16(W[(size_t)k * 512 + n], h, l);
            g_wtgh[ty][(size_t)n*768 + k] = h;
            g_wtgl[ty][(size_t)n*768 + k] = l;
        }
    } else {
        if (n < RCLS) {
            for (int k = threadIdx.x; k < 512; k += 256) {
                __nv_bfloat16 h, l; split_bf16(Wr[(size_t)k * RCLS + n], h, l);
                g_wtrh[(size_t)n*512 + k] = h;
                g_wtrl[(size_t)n*512 + k] = l;
            }
        } else if (n >= 256 && n < 256 + CCLS) {
            int nc = n - 256;
            for (int k = threadIdx.x; k < 512; k += 256) {
                __nv_bfloat16 h, l; split_bf16(Wc[(size_t)k * CCLS + nc], h, l);
                g_wtcch[(size_t)nc*512 + k] = h;
                g_wtccl[(size_t)nc*512 + k] = l;
            }
        }
    }
}

// ---------------- conv as 9 shifted GEMMs, HMMA split-bf16, 512 thr ----------------
// grid (2, 72): x = co-half (128 co), y = M-tile of 128 pixels.
__global__ void __launch_bounds__(512, 1) k_conv_wmma(const float* __restrict__ bias) {
    extern __shared__ char dsm_raw[];
    uint32_t raw = s2u(dsm_raw);
    uint32_t pad = (128u - (raw & 127u)) & 127u;
    char* sp = dsm_raw + pad;
    uint32_t spu = raw + pad;

    int t = threadIdx.x, wid = t >> 5;
    int co0 = blockIdx.x * 128;
    int tileM = blockIdx.y;
    int b = tileM / 18, loc0 = (tileM % 18) * 128;
    int wm = wid & 3, wn = wid >> 2;   // warp tile 32x32

    const __nv_bfloat16* inh_b = g_inh + (size_t)b * 2304 * 1024;
    const __nv_bfloat16* inl_b = g_inl + (size_t)b * 2304 * 1024;

    int rowL[2], qL[2], pyL[2], pxL[2];
#pragma unroll
    for (int i = 0; i < 2; i++) {
        int idx = t + 512*i;
        rowL[i] = idx >> 3; qL[i] = idx & 7;
        int l = loc0 + rowL[i];
        pyL[i] = l / 48; pxL[i] = l % 48;
    }

    wmma::fragment<wmma::accumulator, 16, 16, 16, float> acc[2][2];
#pragma unroll
    for (int i = 0; i < 2; i++)
#pragma unroll
        for (int j = 0; j < 2; j++) wmma::fill_fragment(acc[i][j], 0.f);

#define ISSUE_CHUNK(c) do {                                                       \
        int tap_ = (c) >> 4, ci0_ = ((c) & 15) << 6;                              \
        int dy_ = tap_ / 3 - 1, dx_ = tap_ % 3 - 1;                               \
        uint32_t sb_ = spu + ((c) & 1) * CSTG;                                    \
        _Pragma("unroll")                                                         \
        for (int i = 0; i < 2; i++) {                                             \
            int row_ = rowL[i], q_ = qL[i];                                       \
            uint32_t so_ = (uint32_t)(row_*(CLD*2) + q_*16);                      \
            int ys_ = pyL[i] + dy_, xs_ = pxL[i] + dx_;                           \
            bool ok_ = ((unsigned)ys_ < 48u) & ((unsigned)xs_ < 48u);             \
            size_t go_ = ok_ ? ((size_t)(ys_*48 + xs_)*1024 + ci0_ + q_*8) : 0;   \
            int sz_ = ok_ ? 16 : 0;                                               \
            cp16(sb_ + so_,          inh_b + go_, sz_);                           \
            cp16(sb_ + CMAT + so_,   inl_b + go_, sz_);                           \
            size_t wo_ = (size_t)(tap_*256 + co0 + row_)*1024 + ci0_ + q_*8;      \
            cp16f(sb_ + 2*CMAT + so_, g_wh + wo_);                                \
            cp16f(sb_ + 3*CMAT + so_, g_wl + wo_);                                \
        }                                                                         \
    } while (0)

    ISSUE_CHUNK(0);
    cp_commit();

    for (int c = 0; c < 144; c++) {
        if (c + 1 < 144) { ISSUE_CHUNK(c + 1); cp_commit(); cp_wait1(); }
        else             { cp_wait0(); }
        __syncthreads();
        const char* sb = sp + (c & 1) * CSTG;
        const __nv_bfloat16* Ah = (const __nv_bfloat16*)(sb);
        const __nv_bfloat16* Al = (const __nv_bfloat16*)(sb + CMAT);
        const __nv_bfloat16* Bh = (const __nv_bfloat16*)(sb + 2*CMAT);
        const __nv_bfloat16* Bl = (const __nv_bfloat16*)(sb + 3*CMAT);
#pragma unroll
        for (int kk = 0; kk < 64; kk += 16) {
            wmma::fragment<wmma::matrix_a, 16, 16, 16, __nv_bfloat16, wmma::row_major> ah[2], al[2];
            wmma::fragment<wmma::matrix_b, 16, 16, 16, __nv_bfloat16, wmma::col_major> bh[2], bl[2];
#pragma unroll
            for (int i = 0; i < 2; i++) {
                wmma::load_matrix_sync(ah[i], Ah + (wm*32 + i*16)*CLD + kk, CLD);
                wmma::load_matrix_sync(al[i], Al + (wm*32 + i*16)*CLD + kk, CLD);
            }
#pragma unroll
            for (int j = 0; j < 2; j++) {
                wmma::load_matrix_sync(bh[j], Bh + (wn*32 + j*16)*CLD + kk, CLD);
                wmma::load_matrix_sync(bl[j], Bl + (wn*32 + j*16)*CLD + kk, CLD);
            }
#pragma unroll
            for (int i = 0; i < 2; i++)
#pragma unroll
                for (int j = 0; j < 2; j++) {
                    wmma::mma_sync(acc[i][j], ah[i], bh[j], acc[i][j]);
                    wmma::mma_sync(acc[i][j], al[i], bh[j], acc[i][j]);
                    wmma::mma_sync(acc[i][j], ah[i], bl[j], acc[i][j]);
                }
        }
        __syncthreads();
    }
#undef ISSUE_CHUNK

    float* sE = (float*)sp;
#pragma unroll
    for (int i = 0; i < 2; i++)
#pragma unroll
        for (int j = 0; j < 2; j++)
            wmma::store_matrix_sync(sE + (wm*32 + i*16)*128 + wn*32 + j*16,
                                    acc[i][j], 128, wmma::mem_row_major);
    __syncthreads();
#pragma unroll
    for (int r = 0; r < 8; r++) {
        int idx = t + 512*r;
        int row = idx >> 5, col = (idx & 31) * 4;
        float4 v = *(const float4*)&sE[row*128 + col];
        v.x = fmaxf(v.x + bias[co0+col+0], 0.f);
        v.y = fmaxf(v.y + bias[co0+col+1], 0.f);
        v.z = fmaxf(v.z + bias[co0+col+2], 0.f);
        v.w = fmaxf(v.w + bias[co0+col+3], 0.f);
        int pix = b*2304 + loc0 + row;
        *(float4*)&g_dec[(size_t)pix*256 + co0 + col] = v;
    }
}

// ---------------- split-bf16 HMMA GEMM: C[M,N] = A[M,K] * B[N,K]^T ----------------
// EPI 0: fp32 -> C. EPI 1: relu(+bias) -> split bf16 Ch/Cl. EPI 2: leaky(+bias) -> C (runtime N=Nn, guarded).
template<int EPI>
__global__ void __launch_bounds__(512, 1) k_hgemm(const __nv_bfloat16* __restrict__ Agh,
                                                  const __nv_bfloat16* __restrict__ Agl,
                                                  const __nv_bfloat16* __restrict__ Bgh,
                                                  const __nv_bfloat16* __restrict__ Bgl,
                                                  float* C, __nv_bfloat16* Ch, __nv_bfloat16* Cl,
                                                  const float* __restrict__ bias,
                                                  int K, int ldc, int colofs, int Nn) {
    extern __shared__ char dsm_raw[];
    uint32_t raw = s2u(dsm_raw);
    uint32_t pad = (128u - (raw & 127u)) & 127u;
    char* sp = dsm_raw + pad;
    uint32_t spu = raw + pad;

    int t = threadIdx.x, wid = t >> 5;
    int n0 = blockIdx.x * 128, m0 = blockIdx.y * 128;
    int wm = wid & 3, wn = wid >> 2;

    int rowL[2], qL[2];
#pragma unroll
    for (int i = 0; i < 2; i++) {
        int idx = t + 512*i;
        rowL[i] = idx >> 3; qL[i] = idx & 7;
    }

    wmma::fragment<wmma::accumulator, 16, 16, 16, float> acc[2][2];
#pragma unroll
    for (int i = 0; i < 2; i++)
#pragma unroll
        for (int j = 0; j < 2; j++) wmma::fill_fragment(acc[i][j], 0.f);

    int nch = K >> 6;
#define ISSUE_G(c) do {                                                          \
        int k0_ = (c) << 6;                                                      \
        uint32_t sb_ = spu + ((c) & 1) * CSTG;                                   \
        _Pragma("unroll")                                                        \
        for (int i = 0; i < 2; i++) {                                            \
            int row_ = rowL[i], q_ = qL[i];                                      \
            uint32_t so_ = (uint32_t)(row_*(CLD*2) + q_*16);                     \
            size_t ao_ = (size_t)(m0 + row_)*K + k0_ + q_*8;                     \
            cp16f(sb_ + so_,        Agh + ao_);                                  \
            cp16f(sb_ + CMAT + so_, Agl + ao_);                                  \
            int bn_ = n0 + row_; if (bn_ >= Nn) bn_ = Nn - 1;                    \
            size_t bo_ = (size_t)bn_*K + k0_ + q_*8;                             \
            cp16f(sb_ + 2*CMAT + so_, Bgh + bo_);                                \
            cp16f(sb_ + 3*CMAT + so_, Bgl + bo_);                                \
        }                                                                        \
    } while (0)

    ISSUE_G(0);
    cp_commit();
    for (int c = 0; c < nch; c++) {
        if (c + 1 < nch) { ISSUE_G(c + 1); cp_commit(); cp_wait1(); }
        else             { cp_wait0(); }
        __syncthreads();
        const char* sb = sp + (c & 1) * CSTG;
        const __nv_bfloat16* Ah = (const __nv_bfloat16*)(sb);
        const __nv_bfloat16* Al = (const __nv_bfloat16*)(sb + CMAT);
        const __nv_bfloat16* Bh = (const __nv_bfloat16*)(sb + 2*CMAT);
        const __nv_bfloat16* Bl = (const __nv_bfloat16*)(sb + 3*CMAT);
#pragma unroll
        for (int kk = 0; kk < 64; kk += 16) {
            wmma::fragment<wmma::matrix_a, 16, 16, 16, __nv_bfloat16, wmma::row_major> ah[2], al[2];
            wmma::fragment<wmma::matrix_b, 16, 16, 16, __nv_bfloat16, wmma::col_major> bh[2], bl[2];
#pragma unroll
            for (int i = 0; i < 2; i++) {
                wmma::load_matrix_sync(ah[i], Ah + (wm*32 + i*16)*CLD + kk, CLD);
                wmma::load_matrix_sync(al[i], Al + (wm*32 + i*16)*CLD + kk, CLD);
            }
#pragma unroll
            for (int j = 0; j < 2; j++) {
                wmma::load_matrix_sync(bh[j], Bh + (wn*32 + j*16)*CLD + kk, CLD);
                wmma::load_matrix_sync(bl[j], Bl + (wn*32 + j*16)*CLD + kk, CLD);
            }
#pragma unroll
            for (int i = 0; i < 2; i++)
#pragma unroll
                for (int j = 0; j < 2; j++) {
                    wmma::mma_sync(acc[i][j], ah[i], bh[j], acc[i][j]);
                    wmma::mma_sync(acc[i][j], al[i], bh[j], acc[i][j]);
                    wmma::mma_sync(acc[i][j], ah[i], bl[j], acc[i][j]);
                }
        }
        __syncthreads();
    }
#undef ISSUE_G

    float* sE = (float*)sp;
#pragma unroll
    for (int i = 0; i < 2; i++)
#pragma unroll
        for (int j = 0; j < 2; j++)
            wmma::store_matrix_sync(sE + (wm*32 + i*16)*128 + wn*32 + j*16,
                                    acc[i][j], 128, wmma::mem_row_major);
    __syncthreads();
#pragma unroll
    for (int r = 0; r < 8; r++) {
        int idx = t + 512*r;
        int row = idx >> 5, col = (idx & 31) * 4;
        float4 v = *(const float4*)&sE[row*128 + col];
        if (EPI == 0) {
            *(float4*)&C[(size_t)(m0 + row)*ldc + n0 + col] = v;
        } else if (EPI == 1) {
            v.x = fmaxf(v.x + bias[n0+col+0], 0.f);
            v.y = fmaxf(v.y + bias[n0+col+1], 0.f);
            v.z = fmaxf(v.z + bias[n0+col+2], 0.f);
            v.w = fmaxf(v.w + bias[n0+col+3], 0.f);
            __nv_bfloat16 h0,l0,h1,l1,h2,l2,h3,l3;
            split_bf16(v.x,h0,l0); split_bf16(v.y,h1,l1);
            split_bf16(v.z,h2,l2); split_bf16(v.w,h3,l3);
            size_t o = (size_t)(m0 + row)*ldc + colofs + n0 + col;
            __nv_bfloat162* ph = (__nv_bfloat162*)&Ch[o];
            __nv_bfloat162* pl = (__nv_bfloat162*)&Cl[o];
            ph[0] = __nv_bfloat162(h0, h1); ph[1] = __nv_bfloat162(h2, h3);
            pl[0] = __nv_bfloat162(l0, l1); pl[1] = __nv_bfloat162(l2, l3);
        } else {
            float vv[4] = {v.x, v.y, v.z, v.w};
#pragma unroll
            for (int e = 0; e < 4; e++) {
                int n = n0 + col + e;
                if (n < Nn) {
                    float u = vv[e] + bias[n];
                    u = (u >= 0.f) ? u : 0.01f * u;
                    C[(size_t)(m0 + row)*ldc + n] = u;
                }
            }
        }
    }
}

// ---------------- box feature MLP -> fusion split bf16 ----------------
__global__ void k_boxfeat(const float* __restrict__ boxes,
                          const float* __restrict__ Wb, const float* __restrict__ bb) {
    int n = blockIdx.x, co = threadIdx.x;
    float f0 = boxes[n*4+0], f1 = boxes[n*4+1], f2 = boxes[n*4+2], f3 = boxes[n*4+3];
    float cx = (f0 + f2) / 2.0f, cy = (f1 + f3) / 2.0f;
    float b0 = cx / 48.0f, b1 = cy / 48.0f;
    float b2 = (f2 - f0) / 48.0f, b3 = (f3 - f1) / 48.0f;
    float v = bb[co] + b0*Wb[co] + b1*Wb[256+co] + b2*Wb[512+co] + b3*Wb[768+co];
    v = fmaxf(v, 0.f);
    __nv_bfloat16 h, l; split_bf16(v, h, l);
    g_fush[(size_t)n*FUS + co] = h;
    g_fusl[(size_t)n*FUS + co] = l;
}

// ---------------- cx/cy + table extents ----------------
__global__ void k_cxcy(const float* __restrict__ boxes, const float* __restrict__ scales,
                       const float* __restrict__ pdls, const float* __restrict__ pdts) {
    int b = blockIdx.x, i = threadIdx.x;
    float sc = scales[b], pl = pdls[b], pt = pdts[b];
    const float* bx = boxes + ((size_t)b*NN + i)*4;
    float o0 = (bx[0]-pl)/sc, o1 = (bx[1]-pt)/sc, o2 = (bx[2]-pl)/sc, o3 = (bx[3]-pt)/sc;
    g_cx[b*NN+i] = (o0 + o2) * 0.5f;
    g_cy[b*NN+i] = (o1 + o3) * 0.5f;
    __shared__ float sw[512], sh[512];
    sw[i] = fmaxf(o0, o2); sh[i] = fmaxf(o1, o3);
    __syncthreads();
    for (int s = 256; s > 0; s >>= 1) {
        if (i < s) { sw[i] = fmaxf(sw[i], sw[i+s]); sh[i] = fmaxf(sh[i], sh[i+s]); }
        __syncthreads();
    }
    if (i == 0) { g_tbw[b] = sw[0]; g_tbh[b] = sh[0]; }
}

// ---------------- pair attr keys + fused pass-1 hist (smem-privatized) ----------------
__global__ void k_keys() {
    __shared__ unsigned shr[256], shc[256];
    int t = threadIdx.x;
    if (t < 256) { shr[t] = 0u; shc[t] = 0u; }
    __syncthreads();
    int p = blockIdx.x*256 + t;
    int b = blockIdx.y;
    if (p < NPAIR) {
        int i = p / 511, r = p % 511;
        int j = r + (r >= i ? 1 : 0);
        float cys = g_cy[b*NN+i], cyd = g_cy[b*NN+j];
        float cxs = g_cx[b*NN+i], cxd = g_cx[b*NN+j];
        float dr = (cys - cyd) * 5.0f / g_tbh[b];
        float dc = (cxs - cxd) * 5.0f / g_tbw[b];
        float vr = expf(-(dr*dr));
        float vc = expf(-(dc*dc));
        unsigned long long kr = (((unsigned long long)(~__float_as_uint(vr))) << 32) | (unsigned)p;
        unsigned long long kc = (((unsigned long long)(~__float_as_uint(vc))) << 32) | (unsigned)p;
        g_keys[b][p]     = kr;
        g_keys[4 + b][p] = kc;
        atomicAdd(&shr[(unsigned)(kr >> 56)], 1u);
        atomicAdd(&shc[(unsigned)(kc >> 56)], 1u);
    }
    __syncthreads();
    if (t < 256) {
        if (shr[t]) atomicAdd(&g_hist[b][t], shr[t]);
        if (shc[t]) atomicAdd(&g_hist[4 + b][t], shc[t]);
    }
}

// ---------------- radix select: full-array hist (value bytes) ----------------
__global__ void k_hist(int shift) {
    __shared__ unsigned sh[256];
    int seg = blockIdx.y;
    if (threadIdx.x < 256) sh[threadIdx.x] = 0u;
    __syncthreads();
    unsigned long long pref = g_prefix[seg];
    for (int idx = blockIdx.x*blockDim.x + threadIdx.x; idx < NPAIR; idx += gridDim.x*blockDim.x) {
        unsigned long long k = g_keys[seg][idx];
        if ((((k ^ pref) >> shift) >> 8) == 0ULL)
            atomicAdd(&sh[(unsigned)(k >> shift) & 255u], 1u);
    }
    __syncthreads();
    if (threadIdx.x < 256 && sh[threadIdx.x])
        atomicAdd(&g_hist[seg][threadIdx.x], sh[threadIdx.x]);
}

// ---------------- tie-buffer hist (index bytes) ----------------
__global__ void k_histc(int shift) {
    __shared__ unsigned sh[256];
    int seg = blockIdx.y;
    if (threadIdx.x < 256) sh[threadIdx.x] = 0u;
    __syncthreads();
    unsigned long long pref = g_prefix[seg];
    int n = g_ncand[seg];
    for (int idx = blockIdx.x*blockDim.x + threadIdx.x; idx < n; idx += gridDim.x*blockDim.x) {
        unsigned long long k = g_cand[seg][idx];
        if ((((k ^ pref) >> shift) >> 8) == 0ULL)
            atomicAdd(&sh[(unsigned)(k >> shift) & 255u], 1u);
    }
    __syncthreads();
    if (threadIdx.x < 256 && sh[threadIdx.x])
        atomicAdd(&g_hist[seg][threadIdx.x], sh[threadIdx.x]);
}

__global__ void k_scan(int shift) {
    int seg = threadIdx.x;
    if (seg >= 8) return;
    int need = g_kneed[seg];
    unsigned long long pref = g_prefix[seg];
    int cum = 0, chosen = 255, newneed = need;
    bool done = false;
    for (int bin = 0; bin < 256; bin++) {
        int c = (int)g_hist[seg][bin];
        g_hist[seg][bin] = 0u;
        if (!done && cum + c >= need) { chosen = bin; newneed = need - cum; done = true; }
        cum += c;
    }
    g_prefix[seg] = pref | ((unsigned long long)chosen << shift);
    g_kneed[seg] = newneed;
}

// ---------------- split: emit value_top32 < boundary, collect exact-value ties ----------------
__global__ void k_split() {
    int seg = blockIdx.y;
    unsigned bound = (unsigned)(g_prefix[seg] >> 32);
    for (int idx = blockIdx.x*blockDim.x + threadIdx.x; idx < NPAIR; idx += gridDim.x*blockDim.x) {
        unsigned long long k = g_keys[seg][idx];
        unsigned top = (unsigned)(k >> 32);
        if (top < bound) {
            emit_edge(seg, k);
        } else if (top == bound) {
            int pos = atomicAdd(&g_ncand[seg], 1);
            g_cand[seg][pos] = k;
        }
    }
}

// ---------------- final emit over ties ----------------
__global__ void k_emitc() {
    int seg = blockIdx.y;
    unsigned long long pref = g_prefix[seg];
    int n = g_ncand[seg];
    for (int idx = blockIdx.x*blockDim.x + threadIdx.x; idx < n; idx += gridDim.x*blockDim.x) {
        unsigned long long k = g_cand[seg][idx];
        if (k <= pref) emit_edge(seg, k);
    }
}

// ---------------- ROI align 2x2 -> split bf16 ----------------
__global__ void k_roi(const float* __restrict__ boxes) {
    int n = blockIdx.x, c = threadIdx.x;
    int b = n >> 9;
    float x1 = boxes[n*4+0], y1 = boxes[n*4+1], x2 = boxes[n*4+2], y2 = boxes[n*4+3];
    float bw = (x2 - x1) / 2.0f, bh = (y2 - y1) / 2.0f;
    const float* base = g_dec + (size_t)b * HH * WWW * CO;
#pragma unroll
    for (int p = 0; p < 4; p++) {
        float py = y1 + (0.5f + (float)(p >> 1)) * bh;
        float px = x1 + (0.5f + (float)(p & 1)) * bw;
        py = fminf(fmaxf(py, 0.f), 47.f);
        px = fminf(fmaxf(px, 0.f), 47.f);
        int y0 = (int)floorf(py), x0 = (int)floorf(px);
        int y1i = min(y0 + 1, 47), x1i = min(x0 + 1, 47);
        float wy = py - (float)y0, wx = px - (float)x0;
        float f00 = base[(y0*48 + x0 )*CO + c];
        float f01 = base[(y0*48 + x1i)*CO + c];
        float f10 = base[(y1i*48 + x0 )*CO + c];
        float f11 = base[(y1i*48 + x1i)*CO + c];
        float v = f00*(1.f-wy)*(1.f-wx) + f01*(1.f-wy)*wx + f10*wy*(1.f-wx) + f11*wy*wx;
        __nv_bfloat16 h, l; split_bf16(v, h, l);
        g_cnnh[(size_t)n*1024 + p*256 + c] = h;
        g_cnnl[(size_t)n*1024 + p*256 + c] = l;
    }
}

// ---------------- GCN aggregation scatter (4 edges per block) ----------------
__global__ void __launch_bounds__(512) k_agg() {
    int g = threadIdx.x >> 7, j0 = threadIdx.x & 127;
    int e = blockIdx.x * 4 + g, ty = blockIdx.y;
    if (e >= ETOT) return;
    int src = g_esrc[ty][e], dst = g_edst[ty][e];
    float norm = rsqrtf(g_deg[ty][src]) * g_ew[ty][e] * rsqrtf(g_deg[ty][dst]);
    const float* xs = g_xw[ty] + (size_t)src * GOUT;
    float* fd = g_feat[ty] + (size_t)dst * GOUT;
#pragma unroll
    for (int j = j0; j < GOUT; j += 128)
        atomicAdd(&fd[j], norm * xs[j]);
}

// ---------------- bias+relu -> split bf16 features ----------------
__global__ void k_final(const float* __restrict__ bg0, const float* __restrict__ bg1) {
    int i = blockIdx.x*blockDim.x + threadIdx.x;
    if (i < 2*BN*GOUT) {
        int ty = i / (BN*GOUT);
        int r = i % (BN*GOUT);
        int j = r % GOUT;
        float bv = ty ? bg1[j] : bg0[j];
        float v = fmaxf(((float*)g_feat)[i] + bv, 0.f);
        __nv_bfloat16 h, l; split_bf16(v, h, l);
        ((__nv_bfloat16*)g_feath)[i] = h;
        ((__nv_bfloat16*)g_featl)[i] = l;
    }
}

// ---------------- launch ----------------
extern "C" void kernel_launch(void* const* d_in, const int* in_sizes, int n_in,
                              void* d_out, int out_size) {
    const float* input  = (const float*)d_in[0];
    const float* boxes  = (const float*)d_in[1];
    const float* scales = (const float*)d_in[2];
    const float* pdls   = (const float*)d_in[3];
    const float* pdts   = (const float*)d_in[4];
    const float* W_dec  = (const float*)d_in[5];
    const float* b_dec  = (const float*)d_in[6];
    const float* W_box  = (const float*)d_in[7];
    const float* b_box  = (const float*)d_in[8];
    const float* W_cnn  = (const float*)d_in[9];
    const float* b_cnn  = (const float*)d_in[10];
    const float* W_grow = (const float*)d_in[11];
    const float* b_grow = (const float*)d_in[12];
    const float* W_gcol = (const float*)d_in[13];
    const float* b_gcol = (const float*)d_in[14];
    const float* W_rcls = (const float*)d_in[15];
    const float* b_rcls = (const float*)d_in[16];
    const float* W_ccls = (const float*)d_in[17];
    const float* b_ccls = (const float*)d_in[18];
    float* out = (float*)d_out;

    void *p1, *p2, *p3, *p4, *p5, *p6, *p7, *p8, *p9, *pb, *pc, *pd, *pe, *pf, *pg;
    cudaGetSymbolAddress(&p1, g_cnnh);  cudaGetSymbolAddress(&p2, g_cnnl);
    cudaGetSymbolAddress(&p3, g_fush);  cudaGetSymbolAddress(&p4, g_fusl);
    cudaGetSymbolAddress(&p5, g_wtch);  cudaGetSymbolAddress(&p6, g_wtcl);
    cudaGetSymbolAddress(&p7, g_wtgh);  cudaGetSymbolAddress(&p8, g_wtgl);
    cudaGetSymbolAddress(&p9, g_xw);
    cudaGetSymbolAddress(&pb, g_feath); cudaGetSymbolAddress(&pc, g_featl);
    cudaGetSymbolAddress(&pd, g_wtrh);  cudaGetSymbolAddress(&pe, g_wtrl);
    cudaGetSymbolAddress(&pf, g_wtcch); cudaGetSymbolAddress(&pg, g_wtccl);
    __nv_bfloat16* cnnh = (__nv_bfloat16*)p1;
    __nv_bfloat16* cnnl = (__nv_bfloat16*)p2;
    __nv_bfloat16* fush = (__nv_bfloat16*)p3;
    __nv_bfloat16* fusl = (__nv_bfloat16*)p4;
    __nv_bfloat16* wtch = (__nv_bfloat16*)p5;
    __nv_bfloat16* wtcl = (__nv_bfloat16*)p6;
    __nv_bfloat16* wtgh = (__nv_bfloat16*)p7;
    __nv_bfloat16* wtgl = (__nv_bfloat16*)p8;
    float* xw0 = (float*)p9;
    float* xw1 = xw0 + (size_t)BN*GOUT;
    __nv_bfloat16* feath = (__nv_bfloat16*)pb;
    __nv_bfloat16* featl = (__nv_bfloat16*)pc;
    __nv_bfloat16* wtrh = (__nv_bfloat16*)pd;
    __nv_bfloat16* wtrl = (__nv_bfloat16*)pe;
    __nv_bfloat16* wtcch = (__nv_bfloat16*)pf;
    __nv_bfloat16* wtccl = (__nv_bfloat16*)pg;

    cudaFuncSetAttribute(k_conv_wmma, cudaFuncAttributeMaxDynamicSharedMemorySize, CSMEM);
    cudaFuncSetAttribute(k_hgemm<0>, cudaFuncAttributeMaxDynamicSharedMemorySize, CSMEM);
    cudaFuncSetAttribute(k_hgemm<1>, cudaFuncAttributeMaxDynamicSharedMemorySize, CSMEM);
    cudaFuncSetAttribute(k_hgemm<2>, cudaFuncAttributeMaxDynamicSharedMemorySize, CSMEM);

    // conv moved to 4th launch slot so the fixed-index ncu capture profiles it
    k_init<<<8192, 256>>>();
    k_cvt_in<<<dim3(16, 3, BB*48), 256>>>(input);
    k_cvt_w<<<CO, 256>>>(W_dec);
    k_conv_wmma<<<dim3(2, 72), 512, CSMEM>>>(b_dec);
    k_cvt_misc<<<dim3(512, 4), 256>>>(W_cnn, W_grow, W_gcol, W_rcls, W_ccls);
    k_boxfeat<<<BN, 256>>>(boxes, W_box, b_box);
    k_cxcy<<<BB, 512>>>(boxes, scales, pdls, pdts);
    // --- top-k select ---
    k_keys<<<dim3(1022, 4), 256>>>();
    k_scan<<<1, 8>>>(56);
    k_hist<<<dim3(64, 8), 256>>>(48);  k_scan<<<1, 8>>>(48);
    k_hist<<<dim3(64, 8), 256>>>(40);  k_scan<<<1, 8>>>(40);
    k_hist<<<dim3(64, 8), 256>>>(32);  k_scan<<<1, 8>>>(32);
    k_split<<<dim3(64, 8), 256>>>();
    k_histc<<<dim3(8, 8), 256>>>(16);  k_scan<<<1, 8>>>(16);
    k_histc<<<dim3(8, 8), 256>>>(8);   k_scan<<<1, 8>>>(8);
    k_histc<<<dim3(8, 8), 256>>>(0);   k_scan<<<1, 8>>>(0);
    k_emitc<<<dim3(8, 8), 256>>>();
    k_roi<<<BN, 256>>>(boxes);
    k_hgemm<1><<<dim3(4, 16), 512, CSMEM>>>(cnnh, cnnl, wtch, wtcl,
                                            nullptr, fush, fusl, b_cnn, 1024, FUS, 256, 512);
    k_hgemm<0><<<dim3(4, 16), 512, CSMEM>>>(fush, fusl, wtgh, wtgl,
                                            xw0, nullptr, nullptr, nullptr, 768, 512, 0, 512);
    k_hgemm<0><<<dim3(4, 16), 512, CSMEM>>>(fush, fusl, wtgh + (size_t)512*768, wtgl + (size_t)512*768,
                                            xw1, nullptr, nullptr, nullptr, 768, 512, 0, 512);
    k_agg<<<dim3((ETOT + 3)/4, 2), 512>>>();
    k_final<<<(2*BN*GOUT + 255)/256, 256>>>(b_grow, b_gcol);
    // classifiers on HMMA (leaky relu, runtime N)
    k_hgemm<2><<<dim3(2, 16), 512, CSMEM>>>(feath, featl, wtrh, wtrl,
                                            out, nullptr, nullptr, b_rcls, 512, RCLS, 0, RCLS);
    k_hgemm<2><<<dim3(1, 16), 512, CSMEM>>>(feath + (size_t)BN*GOUT, featl + (size_t)BN*GOUT,
                                            wtcch, wtccl,
                                            out + (size_t)BN*RCLS, nullptr, nullptr, b_ccls, 512, CCLS, 0, CCLS);
}